// round 14
// baseline (speedup 1.0000x reference)
#include <cuda_runtime.h>
#include <cuda_bf16.h>
#include <math.h>

#define Bz   4
#define Cc   256
#define Hh   48
#define Ww   48
#define HW   2304
#define Stok 2484
#define NW   78      // ceil(S/32) mask words per row
#define KPAD 2496    // 39 * 64
#define BOT  64

typedef __nv_bfloat16 bf16;

// ---------------- scratch (device globals; zero-initialized, no allocs) ----------------
__device__ float g_xp [(size_t)Bz*HW*Cc];
__device__ bf16  g_f  [(size_t)Bz*Stok*Cc];    // LN features (bf16)
__device__ float g_q  [(size_t)Bz*HW*Cc];      // Q, local tokens only, f32
__device__ bf16  g_ob [(size_t)Bz*HW*Cc];      // attention out (bf16)
__device__ float g_op [(size_t)Bz*HW*Cc];
__device__ bf16  g_hid[(size_t)Bz*HW*Cc];      // ln_out (bf16)
__device__ bf16  g_m1 [(size_t)Bz*HW*BOT];     // gelu(mlp1) (bf16)
__device__ unsigned g_mb[(size_t)Stok*NW];
__device__ bf16 g_Kb [(size_t)Bz*8*KPAD*32];   // [b][h][key][32]
__device__ bf16 g_Vb [(size_t)Bz*8*KPAD*32];   // [b][h][key][32] (pre-transpose)
__device__ bf16 g_VbT[(size_t)Bz*8*32*KPAD];   // [b][h][32][key]
__device__ bf16 g_wqkv[768*256];               // converted weights
__device__ bf16 g_wout[256*256];
__device__ bf16 g_wm1 [BOT*256];
__device__ bf16 g_wm2 [256*BOT];

// ---------------- small helpers ----------------
__device__ __forceinline__ void cpa16(void* dst, const void* src) {
    unsigned d = (unsigned)__cvta_generic_to_shared(dst);
    asm volatile("cp.async.cg.shared.global [%0], [%1], 16;" :: "r"(d), "l"(src));
}
__device__ __forceinline__ void cpa16z(void* dst, const void* src, int sz) {
    unsigned d = (unsigned)__cvta_generic_to_shared(dst);
    asm volatile("cp.async.cg.shared.global [%0], [%1], 16, %2;" :: "r"(d), "l"(src), "r"(sz));
}
__device__ __forceinline__ void cpa_commit() { asm volatile("cp.async.commit_group;"); }
__device__ __forceinline__ void cpa_wait0()  { asm volatile("cp.async.wait_group 0;"); }
__device__ __forceinline__ void cpa_wait1()  { asm volatile("cp.async.wait_group 1;"); }

__device__ __forceinline__ void mma_tf32(float c[4], const float a[4], float b0, float b1) {
    const unsigned* A = reinterpret_cast<const unsigned*>(a);
    unsigned B0 = __float_as_uint(b0), B1 = __float_as_uint(b1);
    asm volatile(
        "mma.sync.aligned.m16n8k8.row.col.f32.tf32.tf32.f32 "
        "{%0,%1,%2,%3},{%4,%5,%6,%7},{%8,%9},{%0,%1,%2,%3};"
        : "+f"(c[0]), "+f"(c[1]), "+f"(c[2]), "+f"(c[3])
        : "r"(A[0]), "r"(A[1]), "r"(A[2]), "r"(A[3]), "r"(B0), "r"(B1));
}
__device__ __forceinline__ void mma_bf16(float c[4], const unsigned a[4],
                                         unsigned b0, unsigned b1) {
    asm volatile(
        "mma.sync.aligned.m16n8k16.row.col.f32.bf16.bf16.f32 "
        "{%0,%1,%2,%3},{%4,%5,%6,%7},{%8,%9},{%0,%1,%2,%3};"
        : "+f"(c[0]), "+f"(c[1]), "+f"(c[2]), "+f"(c[3])
        : "r"(a[0]), "r"(a[1]), "r"(a[2]), "r"(a[3]), "r"(b0), "r"(b1));
}
__device__ __forceinline__ unsigned pkbf(float lo, float hi) {
    __nv_bfloat162 h = __float22bfloat162_rn(make_float2(lo, hi));
    return *reinterpret_cast<unsigned*>(&h);
}

// ---------------- pack mask -> bitmask, with inline dtype probe ----------------
__global__ void k_pack_mask(const void* __restrict__ mv, unsigned* __restrict__ out) {
    __shared__ int bad_i32, bad_f32;
    if (threadIdx.x == 0) { bad_i32 = 0; bad_f32 = 0; }
    __syncthreads();
    {
        const unsigned* m = (const unsigned*)mv;
        for (int i = threadIdx.x; i < Stok / 4; i += blockDim.x) {
            unsigned v = m[i];
            if (v != 0u && v != 1u)           bad_i32 = 1;   // benign race: all write 1
            if (v != 0u && v != 0x3F800000u)  bad_f32 = 1;
        }
    }
    __syncthreads();
    int dt = (!bad_i32) ? 1 : ((!bad_f32) ? 2 : 0);

    int idx = blockIdx.x * blockDim.x + threadIdx.x;
    if (idx >= Stok * NW) return;
    int q = idx / NW, w = idx % NW;
    unsigned bits = 0;
    int c0 = w * 32;
    const unsigned char* mu = (const unsigned char*)mv;
    const int*           mi = (const int*)mv;
    const float*         mf = (const float*)mv;
    #pragma unroll 4
    for (int j = 0; j < 32; j++) {
        int c = c0 + j;
        bool blk;
        if (c >= Stok)      blk = true;
        else if (dt == 1)   blk = mi[(size_t)q * Stok + c] != 0;
        else if (dt == 2)   blk = mf[(size_t)q * Stok + c] != 0.0f;
        else                blk = mu[(size_t)q * Stok + c] != 0;
        if (blk) bits |= 1u << j;
    }
    out[idx] = bits;
}

// ---------------- all weight conversions in ONE launch ----------------
#define WQKV_N (768*256)
#define WOUT_N (256*256)
#define WM1_N  (BOT*256)
#define WM2_N  (256*BOT)
#define WTOT   (WQKV_N + WOUT_N + WM1_N + WM2_N)

__global__ void k_cvtw_all(const float* __restrict__ s0, const float* __restrict__ s1,
                           const float* __restrict__ s2, const float* __restrict__ s3)
{
    int i = (blockIdx.x * blockDim.x + threadIdx.x) * 4;
    const float* src; bf16* dst; int base;
    if (i < WQKV_N)                       { src = s0; dst = g_wqkv; base = 0; }
    else if (i < WQKV_N + WOUT_N)         { src = s1; dst = g_wout; base = WQKV_N; }
    else if (i < WQKV_N + WOUT_N + WM1_N) { src = s2; dst = g_wm1;  base = WQKV_N + WOUT_N; }
    else if (i < WTOT)                    { src = s3; dst = g_wm2;  base = WQKV_N + WOUT_N + WM1_N; }
    else return;
    int k = i - base;
    float4 v = *(const float4*)(src + k);
    *(uint2*)(dst + k) = make_uint2(pkbf(v.x, v.y), pkbf(v.z, v.w));
}

// ---------------- tf32 mma GEMM for conv (fused transpose A) ----------------
__device__ __forceinline__ float gelu_exact(float v) {
    return 0.5f * v * (1.0f + erff(v * 0.70710678118654752f));
}

__global__ void __launch_bounds__(256) k_conv(
    const float* __restrict__ A, const float* __restrict__ W,
    const float* __restrict__ bias, float* __restrict__ C,
    int M, int N, int K)
{
    __shared__ __align__(16) float As[3][16 * 136];
    __shared__ __align__(16) float Bs[3][64 * 20];
    int tid = threadIdx.x;
    int warp = tid >> 5, lane = tid & 31;
    int g = lane >> 2, t4 = lane & 3;
    int m0 = blockIdx.y * 128, n0 = blockIdx.x * 64;
    int bb = m0 / HW, p0 = m0 % HW;

    auto issue = [&](int k0, int st) {
        #pragma unroll
        for (int r = 0; r < 2; r++) {
            int i = tid + r * 256;
            int kk = i >> 5, c = i & 31;
            const float* src = A + ((size_t)bb * Cc + k0 + kk) * HW + p0 + c * 4;
            cpa16(&As[st][kk * 136 + c * 4], src);
        }
        {
            int row = tid >> 2, c = tid & 3;
            cpa16(&Bs[st][row * 20 + c * 4], W + (size_t)(n0 + row) * K + k0 + c * 4);
        }
        cpa_commit();
    };

    float acc[8][4] = {};
    int nk = K >> 4;
    issue(0, 0);
    issue(16, 1);

    int st = 0;
    for (int ki = 0; ki < nk; ki++) {
        if (ki + 1 < nk) cpa_wait1(); else cpa_wait0();
        __syncthreads();
        if (ki + 2 < nk) {
            int nst = st + 2; if (nst >= 3) nst -= 3;
            issue((ki + 2) << 4, nst);
        }
        const float* as = As[st];
        const float* bs = Bs[st];
        if (++st == 3) st = 0;

        float a[2][4];
        #pragma unroll
        for (int ks = 0; ks < 2; ks++) {
            a[ks][0] = as[(ks * 8 + t4) * 136 + warp * 16 + g];
            a[ks][1] = as[(ks * 8 + t4) * 136 + warp * 16 + 8 + g];
            a[ks][2] = as[(ks * 8 + t4 + 4) * 136 + warp * 16 + g];
            a[ks][3] = as[(ks * 8 + t4 + 4) * 136 + warp * 16 + 8 + g];
        }
        #pragma unroll
        for (int n8 = 0; n8 < 8; n8++) {
            #pragma unroll
            for (int ks = 0; ks < 2; ks++) {
                float b0 = bs[(n8 * 8 + g) * 20 + ks * 8 + t4];
                float b1 = bs[(n8 * 8 + g) * 20 + ks * 8 + t4 + 4];
                mma_tf32(acc[n8], a[ks], b0, b1);
            }
        }
    }

    int gm0 = m0 + warp * 16 + g;
    int gm1 = gm0 + 8;
    #pragma unroll
    for (int n8 = 0; n8 < 8; n8++) {
        int col = n0 + n8 * 8 + 2 * t4;
        float2 bb2 = *(const float2*)(bias + col);
        *(float2*)(C + (size_t)gm0 * N + col) = make_float2(acc[n8][0] + bb2.x, acc[n8][1] + bb2.y);
        *(float2*)(C + (size_t)gm1 * N + col) = make_float2(acc[n8][2] + bb2.x, acc[n8][3] + bb2.y);
    }
}

// ---------------- bf16 mma GEMM, 3-stage cp.async pipeline ----------------
// MODE=0: f32 C. MODE=1: qkv split (Q->f32 compact C, K/V->g_Kb/g_Vb bf16).
// MODE=2: f32 C = acc + bias + D. MODE=3: bf16 C.
// MODE=4: transposed final store: out[b][c][p] = acc + bias + D[p][c] + X[b][c][p].
template<int ACT, int MODE>
__global__ void __launch_bounds__(256) k_bgemm(
    const bf16* __restrict__ A, const bf16* __restrict__ W,
    const float* __restrict__ bias, const float* __restrict__ D,
    const float* __restrict__ X, void* __restrict__ Cv, int M, int N, int K)
{
    __shared__ __align__(16) unsigned As[3][128 * 20];
    __shared__ __align__(16) unsigned Bs[3][64 * 20];
    int tid = threadIdx.x;
    int warp = tid >> 5, lane = tid & 31;
    int g = lane >> 2, t4 = lane & 3;
    int m0 = blockIdx.y * 128, n0 = blockIdx.x * 64;

    auto issue = [&](int k0, int st) {
        #pragma unroll
        for (int i = tid; i < 512; i += 256) {
            int row = i >> 2, c = i & 3;
            int gm = m0 + row;
            int ok = gm < M;
            const bf16* src = A + (size_t)(ok ? gm : 0) * K + k0 + c * 8;
            cpa16z(&As[st][row * 20 + c * 4], src, ok ? 16 : 0);
        }
        {
            int row = tid >> 2, c = tid & 3;
            cpa16(&Bs[st][row * 20 + c * 4], W + (size_t)(n0 + row) * K + k0 + c * 8);
        }
        cpa_commit();
    };

    float acc[8][4] = {};
    int nk = K >> 5;
    issue(0, 0);
    if (nk > 1) issue(32, 1);

    int st = 0;
    for (int ki = 0; ki < nk; ki++) {
        if (ki + 1 < nk) cpa_wait1(); else cpa_wait0();
        __syncthreads();
        if (ki + 2 < nk) {
            int nst = st + 2; if (nst >= 3) nst -= 3;
            issue((ki + 2) << 5, nst);
        }
        const unsigned* as = As[st];
        const unsigned* bs = Bs[st];
        if (++st == 3) st = 0;

        unsigned a[2][4];
        #pragma unroll
        for (int ks = 0; ks < 2; ks++) {
            a[ks][0] = as[(warp * 16 + g) * 20 + ks * 8 + t4];
            a[ks][1] = as[(warp * 16 + 8 + g) * 20 + ks * 8 + t4];
            a[ks][2] = as[(warp * 16 + g) * 20 + ks * 8 + t4 + 4];
            a[ks][3] = as[(warp * 16 + 8 + g) * 20 + ks * 8 + t4 + 4];
        }
        #pragma unroll
        for (int n8 = 0; n8 < 8; n8++) {
            #pragma unroll
            for (int ks = 0; ks < 2; ks++) {
                unsigned b0 = bs[(n8 * 8 + g) * 20 + ks * 8 + t4];
                unsigned b1 = bs[(n8 * 8 + g) * 20 + ks * 8 + t4 + 4];
                mma_bf16(acc[n8], a[ks], b0, b1);
            }
        }
    }

    int gm0 = m0 + warp * 16 + g;
    int gm1 = gm0 + 8;

    if (MODE == 1) {
        float* C = (float*)Cv;
        int region = n0 >> 8;    // 0=Q, 1=K, 2=V
        int b0i = gm0 / Stok, s0 = gm0 - b0i * Stok;
        int b1i = gm1 / Stok, s1 = gm1 - b1i * Stok;
        #pragma unroll
        for (int n8 = 0; n8 < 8; n8++) {
            int col = n0 + n8 * 8 + 2 * t4;
            float2 bb2 = *(const float2*)(bias + col);
            float v0 = acc[n8][0] + bb2.x, v1 = acc[n8][1] + bb2.y;
            float v2 = acc[n8][2] + bb2.x, v3 = acc[n8][3] + bb2.y;
            if (region == 0) {
                if (gm0 < M && s0 < HW)
                    *(float2*)(C + ((size_t)b0i * HW + s0) * 256 + col) = make_float2(v0, v1);
                if (gm1 < M && s1 < HW)
                    *(float2*)(C + ((size_t)b1i * HW + s1) * 256 + col) = make_float2(v2, v3);
            } else {
                int dd = col & 31, hh = (col >> 5) & 7;
                bf16* dst = (region == 1) ? g_Kb : g_Vb;
                if (gm0 < M)
                    *(unsigned*)(dst + ((size_t)(b0i * 8 + hh) * KPAD + s0) * 32 + dd) = pkbf(v0, v1);
                if (gm1 < M)
                    *(unsigned*)(dst + ((size_t)(b1i * 8 + hh) * KPAD + s1) * 32 + dd) = pkbf(v2, v3);
            }
        }
        return;
    }

    if (MODE == 4) {
        float* C = (float*)Cv;
        int b0i = gm0 / HW, p0 = gm0 - b0i * HW;
        int b1i = gm1 / HW, p1 = gm1 - b1i * HW;
        #pragma unroll
        for (int n8 = 0; n8 < 8; n8++) {
            int col = n0 + n8 * 8 + 2 * t4;
            float2 bb2 = *(const float2*)(bias + col);
            float2 d0 = *(const float2*)(D + (size_t)gm0 * N + col);
            float2 d1 = *(const float2*)(D + (size_t)gm1 * N + col);
            size_t i00 = ((size_t)b0i * Cc + col) * HW + p0;
            size_t i01 = ((size_t)b0i * Cc + col + 1) * HW + p0;
            size_t i10 = ((size_t)b1i * Cc + col) * HW + p1;
            size_t i11 = ((size_t)b1i * Cc + col + 1) * HW + p1;
            C[i00] = acc[n8][0] + bb2.x + d0.x + X[i00];
            C[i01] = acc[n8][1] + bb2.y + d0.y + X[i01];
            C[i10] = acc[n8][2] + bb2.x + d1.x + X[i10];
            C[i11] = acc[n8][3] + bb2.y + d1.y + X[i11];
        }
        return;
    }

    #pragma unroll
    for (int n8 = 0; n8 < 8; n8++) {
        int col = n0 + n8 * 8 + 2 * t4;
        float2 bb2 = *(const float2*)(bias + col);
        float v0 = acc[n8][0] + bb2.x, v1 = acc[n8][1] + bb2.y;
        float v2 = acc[n8][2] + bb2.x, v3 = acc[n8][3] + bb2.y;
        if (ACT == 1) {
            v0 = gelu_exact(v0); v1 = gelu_exact(v1);
            v2 = gelu_exact(v2); v3 = gelu_exact(v3);
        }
        if (MODE == 2) {
            if (gm0 < M) {
                float2 d0 = *(const float2*)(D + (size_t)gm0 * N + col);
                v0 += d0.x; v1 += d0.y;
            }
            if (gm1 < M) {
                float2 d1 = *(const float2*)(D + (size_t)gm1 * N + col);
                v2 += d1.x; v3 += d1.y;
            }
        }
        if (MODE == 3) {
            bf16* C = (bf16*)Cv;
            if (gm0 < M) *(unsigned*)(C + (size_t)gm0 * N + col) = pkbf(v0, v1);
            if (gm1 < M) *(unsigned*)(C + (size_t)gm1 * N + col) = pkbf(v2, v3);
        } else {
            float* C = (float*)Cv;
            if (gm0 < M) *(float2*)(C + (size_t)gm0 * N + col) = make_float2(v0, v1);
            if (gm1 < M) *(float2*)(C + (size_t)gm1 * N + col) = make_float2(v2, v3);
        }
    }
}

// ---------------- warp-per-row layernorm over C=256 (bf16 output) ----------------
__global__ void k_ln(const float* __restrict__ in, int inTok,
                     const float* __restrict__ w, const float* __restrict__ bv,
                     bf16* __restrict__ out, int outTok)
{
    int row = blockIdx.x * 8 + (threadIdx.x >> 5);
    int lane = threadIdx.x & 31;
    int b = row / HW, p = row % HW;
    const float* src = in + ((size_t)b * inTok + p) * Cc;
    float4 v0 = *(const float4*)(src + lane * 4);
    float4 v1 = *(const float4*)(src + 128 + lane * 4);
    float s = v0.x + v0.y + v0.z + v0.w + v1.x + v1.y + v1.z + v1.w;
    #pragma unroll
    for (int o = 16; o > 0; o >>= 1) s += __shfl_xor_sync(0xffffffffu, s, o);
    float mean = s * (1.0f / 256.0f);
    float d0x = v0.x - mean, d0y = v0.y - mean, d0z = v0.z - mean, d0w = v0.w - mean;
    float d1x = v1.x - mean, d1y = v1.y - mean, d1z = v1.z - mean, d1w = v1.w - mean;
    float s2 = d0x*d0x + d0y*d0y + d0z*d0z + d0w*d0w
             + d1x*d1x + d1y*d1y + d1z*d1z + d1w*d1w;
    #pragma unroll
    for (int o = 16; o > 0; o >>= 1) s2 += __shfl_xor_sync(0xffffffffu, s2, o);
    float rs = rsqrtf(s2 * (1.0f / 256.0f) + 1e-5f);
    float4 w0 = *(const float4*)(w + lane * 4);
    float4 w1 = *(const float4*)(w + 128 + lane * 4);
    float4 b0 = *(const float4*)(bv + lane * 4);
    float4 b1 = *(const float4*)(bv + 128 + lane * 4);
    bf16* dst = out + ((size_t)b * outTok + p) * Cc;
    uint2 r0 = make_uint2(pkbf(d0x*rs*w0.x + b0.x, d0y*rs*w0.y + b0.y),
                          pkbf(d0z*rs*w0.z + b0.z, d0w*rs*w0.w + b0.w));
    uint2 r1 = make_uint2(pkbf(d1x*rs*w1.x + b1.x, d1y*rs*w1.y + b1.y),
                          pkbf(d1z*rs*w1.z + b1.z, d1w*rs*w1.w + b1.w));
    *(uint2*)(dst + lane * 4) = r0;
    *(uint2*)(dst + 128 + lane * 4) = r1;
}

// ---------------- pool (ps x ps mean) + layernorm (bf16 output) ----------------
__global__ void k_pool_ln(const float* __restrict__ xp,
                          const float* __restrict__ w, const float* __restrict__ bv,
                          bf16* __restrict__ f, int ps, int off, int reg)
{
    int b = blockIdx.y;
    int t = blockIdx.x;
    int gw = Ww / ps;
    int bh = t / gw, bw = t % gw;
    int c = threadIdx.x;
    float s = 0.f;
    for (int i = 0; i < ps; i++) {
        int prow = (bh * ps + i) * Ww + bw * ps;
        const float* base = xp + ((size_t)b * HW + prow) * Cc + c;
        for (int j = 0; j < ps; j++) s += base[(size_t)j * Cc];
    }
    float v = s / (float)(ps * ps);
    __shared__ float sb[8];
    float ss = v;
    #pragma unroll
    for (int o = 16; o > 0; o >>= 1) ss += __shfl_xor_sync(0xffffffffu, ss, o);
    if ((c & 31) == 0) sb[c >> 5] = ss;
    __syncthreads();
    float tot = 0.f;
    #pragma unroll
    for (int i = 0; i < 8; i++) tot += sb[i];
    float mean = tot * (1.0f / 256.0f);
    __syncthreads();
    float d = v - mean;
    float s2 = d * d;
    #pragma unroll
    for (int o = 16; o > 0; o >>= 1) s2 += __shfl_xor_sync(0xffffffffu, s2, o);
    if ((c & 31) == 0) sb[c >> 5] = s2;
    __syncthreads();
    float tot2 = 0.f;
    #pragma unroll
    for (int i = 0; i < 8; i++) tot2 += sb[i];
    float rs = rsqrtf(tot2 * (1.0f / 256.0f) + 1e-5f);
    f[((size_t)b * Stok + off + t) * Cc + c] =
        __float2bfloat16_rn(d * rs * w[reg * Cc + c] + bv[reg * Cc + c]);
}

// ---------------- transpose V: g_Vb [bh][key][32] -> g_VbT [bh][32][key] ----------------
__global__ void __launch_bounds__(256) k_pack_v(const bf16* __restrict__ Vb,
                                                bf16* __restrict__ VbT)
{
    __shared__ bf16 Vt[64][40];
    int kt = blockIdx.x, h = blockIdx.y, b = blockIdx.z;
    int bh = b * 8 + h;
    int tid = threadIdx.x;
    int key = tid >> 2, d0 = (tid & 3) * 8;
    uint4 v = *(const uint4*)(Vb + ((size_t)bh * KPAD + kt * 64 + key) * 32 + d0);
    *(uint4*)&Vt[key][d0] = v;
    __syncthreads();
    int d = tid >> 3, kq = (tid & 7) * 8;
    bf16 r[8];
    #pragma unroll
    for (int i = 0; i < 8; i++) r[i] = Vt[kq + i][d];
    *(uint4*)(VbT + ((size_t)bh * 32 + d) * KPAD + kt * 64 + kq) = *(uint4*)r;
}

// ---------------- bf16 mma flash attention, BQ=256, 512 threads, 3-stage ----------------
#define KV_TILES 39

__global__ void __launch_bounds__(512, 1) k_attn(const float* __restrict__ qv,
                                                 const bf16* __restrict__ Kb,
                                                 const bf16* __restrict__ VbT,
                                                 const unsigned* __restrict__ mb,
                                                 bf16* __restrict__ out)
{
    __shared__ __align__(16) unsigned char KsB[3][64 * 80];
    __shared__ __align__(16) unsigned char VsB[3][32 * 144];
    __shared__ unsigned Msm[3][512];    // 256 q rows x 2 words

    int tid  = threadIdx.x;
    int warp = tid >> 5, lane = tid & 31;    // 16 warps x 16 q rows = 256
    int g = lane >> 2, t4 = lane & 3;
    int q0 = blockIdx.x * 256, h = blockIdx.y, b = blockIdx.z;
    int bh = b * 8 + h;

    const bf16* Kg = Kb  + (size_t)bh * KPAD * 32;
    const bf16* Vg = VbT + (size_t)bh * 32 * KPAD;
    const float* qb = qv + ((size_t)b * HW) * 256 + h * 32;

    const float SC = 0.17677669529663687f * 1.4426950408889634f;  // 1/sqrt(32)*log2e
    int r0 = q0 + warp * 16 + g;
    int r1 = r0 + 8;

    unsigned qa[2][4];
    #pragma unroll
    for (int ks = 0; ks < 2; ks++) {
        #pragma unroll
        for (int half = 0; half < 2; half++) {
            int kc = ks * 16 + half * 8 + 2 * t4;
            float2 u0 = *(const float2*)(qb + (size_t)r0 * 256 + kc);
            float2 u1 = *(const float2*)(qb + (size_t)r1 * 256 + kc);
            qa[ks][half * 2 + 0] = pkbf(u0.x * SC, u0.y * SC);
            qa[ks][half * 2 + 1] = pkbf(u1.x * SC, u1.y * SC);
        }
    }

    auto issue = [&](int kt) {
        int k0 = kt * 64;
        int st = kt % 3;
        if (tid < 256) {       // K tile: 64 rows x 64B = 256 x 16B chunks
            int row = tid >> 2, c = tid & 3;
            cpa16(&KsB[st][row * 80 + c * 16], Kg + (size_t)(k0 + row) * 32 + c * 8);
        } else {               // V tile: 32 rows x 128B = 256 x 16B chunks
            int t = tid - 256;
            int d = t >> 3, c = t & 7;
            cpa16(&VsB[st][d * 144 + c * 16], Vg + (size_t)d * KPAD + k0 + c * 8);
        }
        cpa_commit();
        {                      // mask: 256 rows x 2 words = 512
            int row = tid >> 1, w = tid & 1;
            Msm[st][row * 2 + w] = mb[(size_t)(q0 + row) * NW + kt * 2 + w];
        }
    };

    float l0 = 0.f, l1 = 0.f;
    float o[4][4] = {};

    issue(0);
    issue(1);
    for (int kt = 0; kt < KV_TILES; kt++) {
        if (kt + 1 < KV_TILES) cpa_wait1(); else cpa_wait0();
        __syncthreads();
        if (kt + 2 < KV_TILES) issue(kt + 2);

        int cur = kt % 3;
        const unsigned* Kw = (const unsigned*)KsB[cur];
        const unsigned* Vw = (const unsigned*)VsB[cur];

        unsigned w00 = Msm[cur][(warp * 16 + g) * 2 + 0];
        unsigned w01 = Msm[cur][(warp * 16 + g) * 2 + 1];
        unsigned w10 = Msm[cur][(warp * 16 + 8 + g) * 2 + 0];
        unsigned w11 = Msm[cur][(warp * 16 + 8 + g) * 2 + 1];

        float rs0 = 0.f, rs1 = 0.f;

        #pragma unroll
        for (int j = 0; j < 4; j++) {
            int n8a = 2 * j, n8b = 2 * j + 1;
            float s0[4] = {0.f, 0.f, 0.f, 0.f};
            float s1[4] = {0.f, 0.f, 0.f, 0.f};
            #pragma unroll
            for (int ks = 0; ks < 2; ks++) {
                mma_bf16(s0, qa[ks], Kw[(n8a * 8 + g) * 20 + ks * 8 + t4],
                                     Kw[(n8a * 8 + g) * 20 + ks * 8 + t4 + 4]);
                mma_bf16(s1, qa[ks], Kw[(n8b * 8 + g) * 20 + ks * 8 + t4],
                                     Kw[(n8b * 8 + g) * 20 + ks * 8 + t4 + 4]);
            }
            unsigned mr0 = (j < 2) ? w00 : w01;
            unsigned mr1 = (j < 2) ? w10 : w11;
            int sha = (n8a * 8 + 2 * t4) & 31;
            int shb = (n8b * 8 + 2 * t4) & 31;
            if ((mr0 >> sha) & 1u)        s0[0] = -1.0e9f;
            if ((mr0 >> (sha + 1)) & 1u)  s0[1] = -1.0e9f;
            if ((mr1 >> sha) & 1u)        s0[2] = -1.0e9f;
            if ((mr1 >> (sha + 1)) & 1u)  s0[3] = -1.0e9f;
            if ((mr0 >> shb) & 1u)        s1[0] = -1.0e9f;
            if ((mr0 >> (shb + 1)) & 1u)  s1[1] = -1.0e9f;
            if ((mr1 >> shb) & 1u)        s1[2] = -1.0e9f;
            if ((mr1 >> (shb + 1)) & 1u)  s1[3] = -1.0e9f;
            s0[0] = exp2f(s0[0]); s0[1] = exp2f(s0[1]);
            s0[2] = exp2f(s0[2]); s0[3] = exp2f(s0[3]);
            s1[0] = exp2f(s1[0]); s1[1] = exp2f(s1[1]);
            s1[2] = exp2f(s1[2]); s1[3] = exp2f(s1[3]);
            rs0 += s0[0] + s0[1] + s1[0] + s1[1];
            rs1 += s0[2] + s0[3] + s1[2] + s1[3];
            unsigned paj[4];
            paj[0] = pkbf(s0[0], s0[1]);
            paj[1] = pkbf(s0[2], s0[3]);
            paj[2] = pkbf(s1[0], s1[1]);
            paj[3] = pkbf(s1[2], s1[3]);
            #pragma unroll
            for (int d8 = 0; d8 < 4; d8++) {
                mma_bf16(o[d8], paj, Vw[(d8 * 8 + g) * 36 + j * 8 + t4],
                                     Vw[(d8 * 8 + g) * 36 + j * 8 + t4 + 4]);
            }
        }
        l0 += rs0;
        l1 += rs1;
    }

    l0 += __shfl_xor_sync(0xffffffffu, l0, 1);
    l0 += __shfl_xor_sync(0xffffffffu, l0, 2);
    l1 += __shfl_xor_sync(0xffffffffu, l1, 1);
    l1 += __shfl_xor_sync(0xffffffffu, l1, 2);
    float inv0 = 1.0f / l0, inv1 = 1.0f / l1;
    #pragma unroll
    for (int d8 = 0; d8 < 4; d8++) {
        int dc = h * 32 + d8 * 8 + 2 * t4;
        *(unsigned*)(out + ((size_t)b * HW + r0) * 256 + dc) =
            pkbf(o[d8][0] * inv0, o[d8][1] * inv0);
        *(unsigned*)(out + ((size_t)b * HW + r1) * 256 + dc) =
            pkbf(o[d8][2] * inv1, o[d8][3] * inv1);
    }
}

// ---------------- launch ----------------
extern "C" void kernel_launch(void* const* d_in, const int* in_sizes, int n_in,
                              void* d_out, int out_size)
{
    const float* x          = (const float*)d_in[0];
    const float* conv_w     = (const float*)d_in[1];
    const float* conv_b     = (const float*)d_in[2];
    const float* ln_local_w = (const float*)d_in[3];
    const float* ln_local_b = (const float*)d_in[4];
    const float* ln_reg_w   = (const float*)d_in[5];
    const float* ln_reg_b   = (const float*)d_in[6];
    const float* in_proj_w  = (const float*)d_in[7];
    const float* in_proj_b  = (const float*)d_in[8];
    const float* out_proj_w = (const float*)d_in[9];
    const float* out_proj_b = (const float*)d_in[10];
    const float* ln_out_w   = (const float*)d_in[11];
    const float* ln_out_b   = (const float*)d_in[12];
    const float* mlp_w1     = (const float*)d_in[13];
    const float* mlp_b1     = (const float*)d_in[14];
    const float* mlp_w2     = (const float*)d_in[15];
    const float* mlp_b2     = (const float*)d_in[16];
    const void*  attn_mask  = (const void*)d_in[17];
    float* out = (float*)d_out;

    float *xp, *q, *op;
    bf16 *f, *ob, *hid, *m1, *Kb, *Vb, *VbT, *wqkv, *wout, *wm1, *wm2;
    unsigned* mbp;
    cudaGetSymbolAddress((void**)&xp,  g_xp);
    cudaGetSymbolAddress((void**)&f,   g_f);
    cudaGetSymbolAddress((void**)&q,   g_q);
    cudaGetSymbolAddress((void**)&ob,  g_ob);
    cudaGetSymbolAddress((void**)&op,  g_op);
    cudaGetSymbolAddress((void**)&hid, g_hid);
    cudaGetSymbolAddress((void**)&m1,  g_m1);
    cudaGetSymbolAddress((void**)&mbp, g_mb);
    cudaGetSymbolAddress((void**)&Kb,  g_Kb);
    cudaGetSymbolAddress((void**)&Vb,  g_Vb);
    cudaGetSymbolAddress((void**)&VbT, g_VbT);
    cudaGetSymbolAddress((void**)&wqkv, g_wqkv);
    cudaGetSymbolAddress((void**)&wout, g_wout);
    cudaGetSymbolAddress((void**)&wm1,  g_wm1);
    cudaGetSymbolAddress((void**)&wm2,  g_wm2);

    // preamble (2 launches)
    k_pack_mask<<<(Stok * NW + 255) / 256, 256>>>(attn_mask, mbp);
    k_cvtw_all<<<(WTOT / 4 + 255) / 256, 256>>>(in_proj_w, out_proj_w, mlp_w1, mlp_w2);

    // conv (1x1), reading x[b][c][p] directly (fused transpose, tf32)
    k_conv<<<dim3(Cc / 64, (Bz * HW) / 128), 256>>>(x, conv_w, conv_b, xp, Bz * HW, Cc, Cc);

    // feats: LN local + pooled LN (bf16 out)
    k_ln<<<Bz * HW / 8, 256>>>(xp, HW, ln_local_w, ln_local_b, f, Stok);
    k_pool_ln<<<dim3(144, Bz), 256>>>(xp, ln_reg_w, ln_reg_b, f, 4, HW, 0);
    k_pool_ln<<<dim3(36,  Bz), 256>>>(xp, ln_reg_w, ln_reg_b, f, 8, HW + 144, 1);

    // qkv bf16 GEMM, split epilogue: Q -> g_q f32 (local only), K/V -> g_Kb/g_Vb bf16
    k_bgemm<0, 1><<<dim3(768 / 64, (Bz * Stok + 127) / 128), 256>>>(
        f, wqkv, in_proj_b, nullptr, nullptr, q, Bz * Stok, 3 * Cc, Cc);

    // transpose V (bf16 -> bf16)
    k_pack_v<<<dim3(KV_TILES, 8, Bz), 256>>>(Vb, VbT);

    // attention — BQ=256, 512 threads; bf16 output
    k_attn<<<dim3(HW / 256, 8, Bz), 512>>>(q, Kb, VbT, mbp, ob);

    // out_proj (bf16 in, f32 out)
    k_bgemm<0, 0><<<dim3(Cc / 64, (Bz * HW) / 128), 256>>>(
        ob, wout, out_proj_b, nullptr, nullptr, op, Bz * HW, Cc, Cc);

    // ln_out on local tokens (bf16 out)
    k_ln<<<Bz * HW / 8, 256>>>(op, HW, ln_out_w, ln_out_b, hid, HW);

    // mlp: mlp1 bf16->bf16 with GELU; mlp2 fused transposed final store (+op residual +x)
    k_bgemm<1, 3><<<dim3(BOT / 64, (Bz * HW) / 128), 256>>>(
        hid, wm1, mlp_b1, nullptr, nullptr, m1, Bz * HW, BOT, Cc);
    k_bgemm<0, 4><<<dim3(Cc / 64, (Bz * HW) / 128), 256>>>(
        m1, wm2, mlp_b2, op, x, out, Bz * HW, Cc, BOT);
}

// round 15
// speedup vs baseline: 1.0425x; 1.0425x over previous
#include <cuda_runtime.h>
#include <cuda_bf16.h>
#include <math.h>

#define Bz   4
#define Cc   256
#define Hh   48
#define Ww   48
#define HW   2304
#define Stok 2484
#define NW   78      // ceil(S/32) mask words per row
#define KPAD 2496    // 39 * 64
#define BOT  64

typedef __nv_bfloat16 bf16;

// ---------------- scratch (device globals; zero-initialized, no allocs) ----------------
__device__ float g_xp [(size_t)Bz*HW*Cc];
__device__ bf16  g_f  [(size_t)Bz*Stok*Cc];    // LN features (bf16)
__device__ float g_q  [(size_t)Bz*HW*Cc];      // Q, local tokens only, f32
__device__ bf16  g_ob [(size_t)Bz*HW*Cc];      // attention out (bf16)
__device__ float g_op [(size_t)Bz*HW*Cc];
__device__ bf16  g_hid[(size_t)Bz*HW*Cc];      // ln_out (bf16)
__device__ bf16  g_m1 [(size_t)Bz*HW*BOT];     // gelu(mlp1) (bf16)
__device__ unsigned g_mb[(size_t)Stok*NW];
__device__ bf16 g_Kb [(size_t)Bz*8*KPAD*32];   // [b][h][key][32]
__device__ bf16 g_VbT[(size_t)Bz*8*32*KPAD];   // [b][h][32][key] (written directly by qkv)
__device__ bf16 g_wqkv[768*256];               // converted weights
__device__ bf16 g_wout[256*256];
__device__ bf16 g_wm1 [BOT*256];
__device__ bf16 g_wm2 [256*BOT];

// ---------------- small helpers ----------------
__device__ __forceinline__ void cpa16(void* dst, const void* src) {
    unsigned d = (unsigned)__cvta_generic_to_shared(dst);
    asm volatile("cp.async.cg.shared.global [%0], [%1], 16;" :: "r"(d), "l"(src));
}
__device__ __forceinline__ void cpa16z(void* dst, const void* src, int sz) {
    unsigned d = (unsigned)__cvta_generic_to_shared(dst);
    asm volatile("cp.async.cg.shared.global [%0], [%1], 16, %2;" :: "r"(d), "l"(src), "r"(sz));
}
__device__ __forceinline__ void cpa_commit() { asm volatile("cp.async.commit_group;"); }
__device__ __forceinline__ void cpa_wait0()  { asm volatile("cp.async.wait_group 0;"); }
__device__ __forceinline__ void cpa_wait1()  { asm volatile("cp.async.wait_group 1;"); }

__device__ __forceinline__ void mma_tf32(float c[4], const float a[4], float b0, float b1) {
    const unsigned* A = reinterpret_cast<const unsigned*>(a);
    unsigned B0 = __float_as_uint(b0), B1 = __float_as_uint(b1);
    asm volatile(
        "mma.sync.aligned.m16n8k8.row.col.f32.tf32.tf32.f32 "
        "{%0,%1,%2,%3},{%4,%5,%6,%7},{%8,%9},{%0,%1,%2,%3};"
        : "+f"(c[0]), "+f"(c[1]), "+f"(c[2]), "+f"(c[3])
        : "r"(A[0]), "r"(A[1]), "r"(A[2]), "r"(A[3]), "r"(B0), "r"(B1));
}
__device__ __forceinline__ void mma_bf16(float c[4], const unsigned a[4],
                                         unsigned b0, unsigned b1) {
    asm volatile(
        "mma.sync.aligned.m16n8k16.row.col.f32.bf16.bf16.f32 "
        "{%0,%1,%2,%3},{%4,%5,%6,%7},{%8,%9},{%0,%1,%2,%3};"
        : "+f"(c[0]), "+f"(c[1]), "+f"(c[2]), "+f"(c[3])
        : "r"(a[0]), "r"(a[1]), "r"(a[2]), "r"(a[3]), "r"(b0), "r"(b1));
}
__device__ __forceinline__ unsigned pkbf(float lo, float hi) {
    __nv_bfloat162 h = __float22bfloat162_rn(make_float2(lo, hi));
    return *reinterpret_cast<unsigned*>(&h);
}

// ---------------- pack mask -> bitmask, with inline dtype probe ----------------
__global__ void k_pack_mask(const void* __restrict__ mv, unsigned* __restrict__ out) {
    __shared__ int bad_i32, bad_f32;
    if (threadIdx.x == 0) { bad_i32 = 0; bad_f32 = 0; }
    __syncthreads();
    {
        const unsigned* m = (const unsigned*)mv;
        for (int i = threadIdx.x; i < Stok / 4; i += blockDim.x) {
            unsigned v = m[i];
            if (v != 0u && v != 1u)           bad_i32 = 1;   // benign race: all write 1
            if (v != 0u && v != 0x3F800000u)  bad_f32 = 1;
        }
    }
    __syncthreads();
    int dt = (!bad_i32) ? 1 : ((!bad_f32) ? 2 : 0);

    int idx = blockIdx.x * blockDim.x + threadIdx.x;
    if (idx >= Stok * NW) return;
    int q = idx / NW, w = idx % NW;
    unsigned bits = 0;
    int c0 = w * 32;
    const unsigned char* mu = (const unsigned char*)mv;
    const int*           mi = (const int*)mv;
    const float*         mf = (const float*)mv;
    #pragma unroll 4
    for (int j = 0; j < 32; j++) {
        int c = c0 + j;
        bool blk;
        if (c >= Stok)      blk = true;
        else if (dt == 1)   blk = mi[(size_t)q * Stok + c] != 0;
        else if (dt == 2)   blk = mf[(size_t)q * Stok + c] != 0.0f;
        else                blk = mu[(size_t)q * Stok + c] != 0;
        if (blk) bits |= 1u << j;
    }
    out[idx] = bits;
}

// ---------------- all weight conversions in ONE launch ----------------
#define WQKV_N (768*256)
#define WOUT_N (256*256)
#define WM1_N  (BOT*256)
#define WM2_N  (256*BOT)
#define WTOT   (WQKV_N + WOUT_N + WM1_N + WM2_N)

__global__ void k_cvtw_all(const float* __restrict__ s0, const float* __restrict__ s1,
                           const float* __restrict__ s2, const float* __restrict__ s3)
{
    int i = (blockIdx.x * blockDim.x + threadIdx.x) * 4;
    const float* src; bf16* dst; int base;
    if (i < WQKV_N)                       { src = s0; dst = g_wqkv; base = 0; }
    else if (i < WQKV_N + WOUT_N)         { src = s1; dst = g_wout; base = WQKV_N; }
    else if (i < WQKV_N + WOUT_N + WM1_N) { src = s2; dst = g_wm1;  base = WQKV_N + WOUT_N; }
    else if (i < WTOT)                    { src = s3; dst = g_wm2;  base = WQKV_N + WOUT_N + WM1_N; }
    else return;
    int k = i - base;
    float4 v = *(const float4*)(src + k);
    *(uint2*)(dst + k) = make_uint2(pkbf(v.x, v.y), pkbf(v.z, v.w));
}

// ---------------- tf32 mma GEMM for conv (fused transpose A) ----------------
__device__ __forceinline__ float gelu_exact(float v) {
    return 0.5f * v * (1.0f + erff(v * 0.70710678118654752f));
}

__global__ void __launch_bounds__(256) k_conv(
    const float* __restrict__ A, const float* __restrict__ W,
    const float* __restrict__ bias, float* __restrict__ C,
    int M, int N, int K)
{
    __shared__ __align__(16) float As[3][16 * 136];
    __shared__ __align__(16) float Bs[3][64 * 20];
    int tid = threadIdx.x;
    int warp = tid >> 5, lane = tid & 31;
    int g = lane >> 2, t4 = lane & 3;
    int m0 = blockIdx.y * 128, n0 = blockIdx.x * 64;
    int bb = m0 / HW, p0 = m0 % HW;

    auto issue = [&](int k0, int st) {
        #pragma unroll
        for (int r = 0; r < 2; r++) {
            int i = tid + r * 256;
            int kk = i >> 5, c = i & 31;
            const float* src = A + ((size_t)bb * Cc + k0 + kk) * HW + p0 + c * 4;
            cpa16(&As[st][kk * 136 + c * 4], src);
        }
        {
            int row = tid >> 2, c = tid & 3;
            cpa16(&Bs[st][row * 20 + c * 4], W + (size_t)(n0 + row) * K + k0 + c * 4);
        }
        cpa_commit();
    };

    float acc[8][4] = {};
    int nk = K >> 4;
    issue(0, 0);
    issue(16, 1);

    int st = 0;
    for (int ki = 0; ki < nk; ki++) {
        if (ki + 1 < nk) cpa_wait1(); else cpa_wait0();
        __syncthreads();
        if (ki + 2 < nk) {
            int nst = st + 2; if (nst >= 3) nst -= 3;
            issue((ki + 2) << 4, nst);
        }
        const float* as = As[st];
        const float* bs = Bs[st];
        if (++st == 3) st = 0;

        float a[2][4];
        #pragma unroll
        for (int ks = 0; ks < 2; ks++) {
            a[ks][0] = as[(ks * 8 + t4) * 136 + warp * 16 + g];
            a[ks][1] = as[(ks * 8 + t4) * 136 + warp * 16 + 8 + g];
            a[ks][2] = as[(ks * 8 + t4 + 4) * 136 + warp * 16 + g];
            a[ks][3] = as[(ks * 8 + t4 + 4) * 136 + warp * 16 + 8 + g];
        }
        #pragma unroll
        for (int n8 = 0; n8 < 8; n8++) {
            #pragma unroll
            for (int ks = 0; ks < 2; ks++) {
                float b0 = bs[(n8 * 8 + g) * 20 + ks * 8 + t4];
                float b1 = bs[(n8 * 8 + g) * 20 + ks * 8 + t4 + 4];
                mma_tf32(acc[n8], a[ks], b0, b1);
            }
        }
    }

    int gm0 = m0 + warp * 16 + g;
    int gm1 = gm0 + 8;
    #pragma unroll
    for (int n8 = 0; n8 < 8; n8++) {
        int col = n0 + n8 * 8 + 2 * t4;
        float2 bb2 = *(const float2*)(bias + col);
        *(float2*)(C + (size_t)gm0 * N + col) = make_float2(acc[n8][0] + bb2.x, acc[n8][1] + bb2.y);
        *(float2*)(C + (size_t)gm1 * N + col) = make_float2(acc[n8][2] + bb2.x, acc[n8][3] + bb2.y);
    }
}

// ---------------- bf16 mma GEMM, 3-stage cp.async pipeline ----------------
// MODE=0: f32 C. MODE=1: qkv split (Q->f32 compact C, K->g_Kb, V->g_VbT transposed).
// MODE=2: f32 C = acc + bias + D. MODE=3: bf16 C.
// MODE=4: transposed final store: out[b][c][p] = acc + bias + D[p][c] + X[b][c][p].
template<int ACT, int MODE>
__global__ void __launch_bounds__(256) k_bgemm(
    const bf16* __restrict__ A, const bf16* __restrict__ W,
    const float* __restrict__ bias, const float* __restrict__ D,
    const float* __restrict__ X, void* __restrict__ Cv, int M, int N, int K)
{
    __shared__ __align__(16) unsigned As[3][128 * 20];
    __shared__ __align__(16) unsigned Bs[3][64 * 20];
    int tid = threadIdx.x;
    int warp = tid >> 5, lane = tid & 31;
    int g = lane >> 2, t4 = lane & 3;
    int m0 = blockIdx.y * 128, n0 = blockIdx.x * 64;

    auto issue = [&](int k0, int st) {
        #pragma unroll
        for (int i = tid; i < 512; i += 256) {
            int row = i >> 2, c = i & 3;
            int gm = m0 + row;
            int ok = gm < M;
            const bf16* src = A + (size_t)(ok ? gm : 0) * K + k0 + c * 8;
            cpa16z(&As[st][row * 20 + c * 4], src, ok ? 16 : 0);
        }
        {
            int row = tid >> 2, c = tid & 3;
            cpa16(&Bs[st][row * 20 + c * 4], W + (size_t)(n0 + row) * K + k0 + c * 8);
        }
        cpa_commit();
    };

    float acc[8][4] = {};
    int nk = K >> 5;
    issue(0, 0);
    if (nk > 1) issue(32, 1);

    int st = 0;
    for (int ki = 0; ki < nk; ki++) {
        if (ki + 1 < nk) cpa_wait1(); else cpa_wait0();
        __syncthreads();
        if (ki + 2 < nk) {
            int nst = st + 2; if (nst >= 3) nst -= 3;
            issue((ki + 2) << 5, nst);
        }
        const unsigned* as = As[st];
        const unsigned* bs = Bs[st];
        if (++st == 3) st = 0;

        unsigned a[2][4];
        #pragma unroll
        for (int ks = 0; ks < 2; ks++) {
            a[ks][0] = as[(warp * 16 + g) * 20 + ks * 8 + t4];
            a[ks][1] = as[(warp * 16 + 8 + g) * 20 + ks * 8 + t4];
            a[ks][2] = as[(warp * 16 + g) * 20 + ks * 8 + t4 + 4];
            a[ks][3] = as[(warp * 16 + 8 + g) * 20 + ks * 8 + t4 + 4];
        }
        #pragma unroll
        for (int n8 = 0; n8 < 8; n8++) {
            #pragma unroll
            for (int ks = 0; ks < 2; ks++) {
                unsigned b0 = bs[(n8 * 8 + g) * 20 + ks * 8 + t4];
                unsigned b1 = bs[(n8 * 8 + g) * 20 + ks * 8 + t4 + 4];
                mma_bf16(acc[n8], a[ks], b0, b1);
            }
        }
    }

    int gm0 = m0 + warp * 16 + g;
    int gm1 = gm0 + 8;

    if (MODE == 1) {
        float* C = (float*)Cv;
        int region = n0 >> 8;    // 0=Q, 1=K, 2=V
        int b0i = gm0 / Stok, s0 = gm0 - b0i * Stok;
        int b1i = gm1 / Stok, s1 = gm1 - b1i * Stok;
        #pragma unroll
        for (int n8 = 0; n8 < 8; n8++) {
            int col = n0 + n8 * 8 + 2 * t4;
            float2 bb2 = *(const float2*)(bias + col);
            float v0 = acc[n8][0] + bb2.x, v1 = acc[n8][1] + bb2.y;
            float v2 = acc[n8][2] + bb2.x, v3 = acc[n8][3] + bb2.y;
            if (region == 0) {
                if (gm0 < M && s0 < HW)
                    *(float2*)(C + ((size_t)b0i * HW + s0) * 256 + col) = make_float2(v0, v1);
                if (gm1 < M && s1 < HW)
                    *(float2*)(C + ((size_t)b1i * HW + s1) * 256 + col) = make_float2(v2, v3);
            } else if (region == 1) {
                int dd = col & 31, hh = (col >> 5) & 7;
                if (gm0 < M)
                    *(unsigned*)(g_Kb + ((size_t)(b0i * 8 + hh) * KPAD + s0) * 32 + dd) = pkbf(v0, v1);
                if (gm1 < M)
                    *(unsigned*)(g_Kb + ((size_t)(b1i * 8 + hh) * KPAD + s1) * 32 + dd) = pkbf(v2, v3);
            } else {
                // V: store directly transposed into g_VbT [bh][d][key]
                int dd = col & 31, hh = (col >> 5) & 7;
                if (gm0 < M) {
                    bf16* base = g_VbT + (size_t)(b0i * 8 + hh) * 32 * KPAD;
                    base[(size_t)dd * KPAD + s0]       = __float2bfloat16_rn(v0);
                    base[(size_t)(dd + 1) * KPAD + s0] = __float2bfloat16_rn(v1);
                }
                if (gm1 < M) {
                    bf16* base = g_VbT + (size_t)(b1i * 8 + hh) * 32 * KPAD;
                    base[(size_t)dd * KPAD + s1]       = __float2bfloat16_rn(v2);
                    base[(size_t)(dd + 1) * KPAD + s1] = __float2bfloat16_rn(v3);
                }
            }
        }
        return;
    }

    if (MODE == 4) {
        float* C = (float*)Cv;
        int b0i = gm0 / HW, p0 = gm0 - b0i * HW;
        int b1i = gm1 / HW, p1 = gm1 - b1i * HW;
        #pragma unroll
        for (int n8 = 0; n8 < 8; n8++) {
            int col = n0 + n8 * 8 + 2 * t4;
            float2 bb2 = *(const float2*)(bias + col);
            float2 d0 = *(const float2*)(D + (size_t)gm0 * N + col);
            float2 d1 = *(const float2*)(D + (size_t)gm1 * N + col);
            size_t i00 = ((size_t)b0i * Cc + col) * HW + p0;
            size_t i01 = ((size_t)b0i * Cc + col + 1) * HW + p0;
            size_t i10 = ((size_t)b1i * Cc + col) * HW + p1;
            size_t i11 = ((size_t)b1i * Cc + col + 1) * HW + p1;
            C[i00] = acc[n8][0] + bb2.x + d0.x + X[i00];
            C[i01] = acc[n8][1] + bb2.y + d0.y + X[i01];
            C[i10] = acc[n8][2] + bb2.x + d1.x + X[i10];
            C[i11] = acc[n8][3] + bb2.y + d1.y + X[i11];
        }
        return;
    }

    #pragma unroll
    for (int n8 = 0; n8 < 8; n8++) {
        int col = n0 + n8 * 8 + 2 * t4;
        float2 bb2 = *(const float2*)(bias + col);
        float v0 = acc[n8][0] + bb2.x, v1 = acc[n8][1] + bb2.y;
        float v2 = acc[n8][2] + bb2.x, v3 = acc[n8][3] + bb2.y;
        if (ACT == 1) {
            v0 = gelu_exact(v0); v1 = gelu_exact(v1);
            v2 = gelu_exact(v2); v3 = gelu_exact(v3);
        }
        if (MODE == 2) {
            if (gm0 < M) {
                float2 d0 = *(const float2*)(D + (size_t)gm0 * N + col);
                v0 += d0.x; v1 += d0.y;
            }
            if (gm1 < M) {
                float2 d1 = *(const float2*)(D + (size_t)gm1 * N + col);
                v2 += d1.x; v3 += d1.y;
            }
        }
        if (MODE == 3) {
            bf16* C = (bf16*)Cv;
            if (gm0 < M) *(unsigned*)(C + (size_t)gm0 * N + col) = pkbf(v0, v1);
            if (gm1 < M) *(unsigned*)(C + (size_t)gm1 * N + col) = pkbf(v2, v3);
        } else {
            float* C = (float*)Cv;
            if (gm0 < M) *(float2*)(C + (size_t)gm0 * N + col) = make_float2(v0, v1);
            if (gm1 < M) *(float2*)(C + (size_t)gm1 * N + col) = make_float2(v2, v3);
        }
    }
}

// ---------------- warp-per-row layernorm over C=256 (bf16 output) ----------------
__global__ void k_ln(const float* __restrict__ in, int inTok,
                     const float* __restrict__ w, const float* __restrict__ bv,
                     bf16* __restrict__ out, int outTok)
{
    int row = blockIdx.x * 8 + (threadIdx.x >> 5);
    int lane = threadIdx.x & 31;
    int b = row / HW, p = row % HW;
    const float* src = in + ((size_t)b * inTok + p) * Cc;
    float4 v0 = *(const float4*)(src + lane * 4);
    float4 v1 = *(const float4*)(src + 128 + lane * 4);
    float s = v0.x + v0.y + v0.z + v0.w + v1.x + v1.y + v1.z + v1.w;
    #pragma unroll
    for (int o = 16; o > 0; o >>= 1) s += __shfl_xor_sync(0xffffffffu, s, o);
    float mean = s * (1.0f / 256.0f);
    float d0x = v0.x - mean, d0y = v0.y - mean, d0z = v0.z - mean, d0w = v0.w - mean;
    float d1x = v1.x - mean, d1y = v1.y - mean, d1z = v1.z - mean, d1w = v1.w - mean;
    float s2 = d0x*d0x + d0y*d0y + d0z*d0z + d0w*d0w
             + d1x*d1x + d1y*d1y + d1z*d1z + d1w*d1w;
    #pragma unroll
    for (int o = 16; o > 0; o >>= 1) s2 += __shfl_xor_sync(0xffffffffu, s2, o);
    float rs = rsqrtf(s2 * (1.0f / 256.0f) + 1e-5f);
    float4 w0 = *(const float4*)(w + lane * 4);
    float4 w1 = *(const float4*)(w + 128 + lane * 4);
    float4 b0 = *(const float4*)(bv + lane * 4);
    float4 b1 = *(const float4*)(bv + 128 + lane * 4);
    bf16* dst = out + ((size_t)b * outTok + p) * Cc;
    uint2 r0 = make_uint2(pkbf(d0x*rs*w0.x + b0.x, d0y*rs*w0.y + b0.y),
                          pkbf(d0z*rs*w0.z + b0.z, d0w*rs*w0.w + b0.w));
    uint2 r1 = make_uint2(pkbf(d1x*rs*w1.x + b1.x, d1y*rs*w1.y + b1.y),
                          pkbf(d1z*rs*w1.z + b1.z, d1w*rs*w1.w + b1.w));
    *(uint2*)(dst + lane * 4) = r0;
    *(uint2*)(dst + 128 + lane * 4) = r1;
}

// ---------------- pool (ps x ps mean) + layernorm (bf16 output) ----------------
__global__ void k_pool_ln(const float* __restrict__ xp,
                          const float* __restrict__ w, const float* __restrict__ bv,
                          bf16* __restrict__ f, int ps, int off, int reg)
{
    int b = blockIdx.y;
    int t = blockIdx.x;
    int gw = Ww / ps;
    int bh = t / gw, bw = t % gw;
    int c = threadIdx.x;
    float s = 0.f;
    for (int i = 0; i < ps; i++) {
        int prow = (bh * ps + i) * Ww + bw * ps;
        const float* base = xp + ((size_t)b * HW + prow) * Cc + c;
        for (int j = 0; j < ps; j++) s += base[(size_t)j * Cc];
    }
    float v = s / (float)(ps * ps);
    __shared__ float sb[8];
    float ss = v;
    #pragma unroll
    for (int o = 16; o > 0; o >>= 1) ss += __shfl_xor_sync(0xffffffffu, ss, o);
    if ((c & 31) == 0) sb[c >> 5] = ss;
    __syncthreads();
    float tot = 0.f;
    #pragma unroll
    for (int i = 0; i < 8; i++) tot += sb[i];
    float mean = tot * (1.0f / 256.0f);
    __syncthreads();
    float d = v - mean;
    float s2 = d * d;
    #pragma unroll
    for (int o = 16; o > 0; o >>= 1) s2 += __shfl_xor_sync(0xffffffffu, s2, o);
    if ((c & 31) == 0) sb[c >> 5] = s2;
    __syncthreads();
    float tot2 = 0.f;
    #pragma unroll
    for (int i = 0; i < 8; i++) tot2 += sb[i];
    float rs = rsqrtf(tot2 * (1.0f / 256.0f) + 1e-5f);
    f[((size_t)b * Stok + off + t) * Cc + c] =
        __float2bfloat16_rn(d * rs * w[reg * Cc + c] + bv[reg * Cc + c]);
}

// ---------------- bf16 mma flash attention, BQ=128, 2 CTAs/SM, 3-stage ----------------
#define KV_TILES 39

__global__ void __launch_bounds__(256, 2) k_attn(const float* __restrict__ qv,
                                                 const bf16* __restrict__ Kb,
                                                 const bf16* __restrict__ VbT,
                                                 const unsigned* __restrict__ mb,
                                                 bf16* __restrict__ out)
{
    __shared__ __align__(16) unsigned char KsB[3][64 * 80];
    __shared__ __align__(16) unsigned char VsB[3][32 * 144];
    __shared__ unsigned Msm[3][256];

    int tid  = threadIdx.x;
    int warp = tid >> 5, lane = tid & 31;
    int g = lane >> 2, t4 = lane & 3;
    int q0 = blockIdx.x * 128, h = blockIdx.y, b = blockIdx.z;
    int bh = b * 8 + h;

    const bf16* Kg = Kb  + (size_t)bh * KPAD * 32;
    const bf16* Vg = VbT + (size_t)bh * 32 * KPAD;
    const float* qb = qv + ((size_t)b * HW) * 256 + h * 32;

    const float SC = 0.17677669529663687f * 1.4426950408889634f;  // 1/sqrt(32)*log2e
    int r0 = q0 + warp * 16 + g;
    int r1 = r0 + 8;

    unsigned qa[2][4];
    #pragma unroll
    for (int ks = 0; ks < 2; ks++) {
        #pragma unroll
        for (int half = 0; half < 2; half++) {
            int kc = ks * 16 + half * 8 + 2 * t4;
            float2 u0 = *(const float2*)(qb + (size_t)r0 * 256 + kc);
            float2 u1 = *(const float2*)(qb + (size_t)r1 * 256 + kc);
            qa[ks][half * 2 + 0] = pkbf(u0.x * SC, u0.y * SC);
            qa[ks][half * 2 + 1] = pkbf(u1.x * SC, u1.y * SC);
        }
    }

    auto issue = [&](int kt) {
        int k0 = kt * 64;
        int st = kt % 3;
        {
            int row = tid >> 2, c = tid & 3;
            cpa16(&KsB[st][row * 80 + c * 16], Kg + (size_t)(k0 + row) * 32 + c * 8);
        }
        {
            int d = tid >> 3, c = tid & 7;
            cpa16(&VsB[st][d * 144 + c * 16], Vg + (size_t)d * KPAD + k0 + c * 8);
        }
        cpa_commit();
        if (tid < 128) {
            int row = tid, gq = q0 + row;
            Msm[st][row * 2]     = mb[(size_t)gq * NW + kt * 2];
            Msm[st][row * 2 + 1] = mb[(size_t)gq * NW + kt * 2 + 1];
        }
    };

    float l0 = 0.f, l1 = 0.f;
    float o[4][4] = {};

    issue(0);
    issue(1);
    for (int kt = 0; kt < KV_TILES; kt++) {
        if (kt + 1 < KV_TILES) cpa_wait1(); else cpa_wait0();
        __syncthreads();
        if (kt + 2 < KV_TILES) issue(kt + 2);

        int cur = kt % 3;
        const unsigned* Kw = (const unsigned*)KsB[cur];
        const unsigned* Vw = (const unsigned*)VsB[cur];

        unsigned w00 = Msm[cur][(warp * 16 + g) * 2 + 0];
        unsigned w01 = Msm[cur][(warp * 16 + g) * 2 + 1];
        unsigned w10 = Msm[cur][(warp * 16 + 8 + g) * 2 + 0];
        unsigned w11 = Msm[cur][(warp * 16 + 8 + g) * 2 + 1];

        float rs0 = 0.f, rs1 = 0.f;

        #pragma unroll
        for (int j = 0; j < 4; j++) {
            int n8a = 2 * j, n8b = 2 * j + 1;
            float s0[4] = {0.f, 0.f, 0.f, 0.f};
            float s1[4] = {0.f, 0.f, 0.f, 0.f};
            #pragma unroll
            for (int ks = 0; ks < 2; ks++) {
                mma_bf16(s0, qa[ks], Kw[(n8a * 8 + g) * 20 + ks * 8 + t4],
                                     Kw[(n8a * 8 + g) * 20 + ks * 8 + t4 + 4]);
                mma_bf16(s1, qa[ks], Kw[(n8b * 8 + g) * 20 + ks * 8 + t4],
                                     Kw[(n8b * 8 + g) * 20 + ks * 8 + t4 + 4]);
            }
            unsigned mr0 = (j < 2) ? w00 : w01;
            unsigned mr1 = (j < 2) ? w10 : w11;
            int sha = (n8a * 8 + 2 * t4) & 31;
            int shb = (n8b * 8 + 2 * t4) & 31;
            if ((mr0 >> sha) & 1u)        s0[0] = -1.0e9f;
            if ((mr0 >> (sha + 1)) & 1u)  s0[1] = -1.0e9f;
            if ((mr1 >> sha) & 1u)        s0[2] = -1.0e9f;
            if ((mr1 >> (sha + 1)) & 1u)  s0[3] = -1.0e9f;
            if ((mr0 >> shb) & 1u)        s1[0] = -1.0e9f;
            if ((mr0 >> (shb + 1)) & 1u)  s1[1] = -1.0e9f;
            if ((mr1 >> shb) & 1u)        s1[2] = -1.0e9f;
            if ((mr1 >> (shb + 1)) & 1u)  s1[3] = -1.0e9f;
            s0[0] = exp2f(s0[0]); s0[1] = exp2f(s0[1]);
            s0[2] = exp2f(s0[2]); s0[3] = exp2f(s0[3]);
            s1[0] = exp2f(s1[0]); s1[1] = exp2f(s1[1]);
            s1[2] = exp2f(s1[2]); s1[3] = exp2f(s1[3]);
            rs0 += s0[0] + s0[1] + s1[0] + s1[1];
            rs1 += s0[2] + s0[3] + s1[2] + s1[3];
            unsigned paj[4];
            paj[0] = pkbf(s0[0], s0[1]);
            paj[1] = pkbf(s0[2], s0[3]);
            paj[2] = pkbf(s1[0], s1[1]);
            paj[3] = pkbf(s1[2], s1[3]);
            #pragma unroll
            for (int d8 = 0; d8 < 4; d8++) {
                mma_bf16(o[d8], paj, Vw[(d8 * 8 + g) * 36 + j * 8 + t4],
                                     Vw[(d8 * 8 + g) * 36 + j * 8 + t4 + 4]);
            }
        }
        l0 += rs0;
        l1 += rs1;
    }

    l0 += __shfl_xor_sync(0xffffffffu, l0, 1);
    l0 += __shfl_xor_sync(0xffffffffu, l0, 2);
    l1 += __shfl_xor_sync(0xffffffffu, l1, 1);
    l1 += __shfl_xor_sync(0xffffffffu, l1, 2);
    float inv0 = 1.0f / l0, inv1 = 1.0f / l1;
    #pragma unroll
    for (int d8 = 0; d8 < 4; d8++) {
        int dc = h * 32 + d8 * 8 + 2 * t4;
        *(unsigned*)(out + ((size_t)b * HW + r0) * 256 + dc) =
            pkbf(o[d8][0] * inv0, o[d8][1] * inv0);
        *(unsigned*)(out + ((size_t)b * HW + r1) * 256 + dc) =
            pkbf(o[d8][2] * inv1, o[d8][3] * inv1);
    }
}

// ---------------- launch ----------------
extern "C" void kernel_launch(void* const* d_in, const int* in_sizes, int n_in,
                              void* d_out, int out_size)
{
    const float* x          = (const float*)d_in[0];
    const float* conv_w     = (const float*)d_in[1];
    const float* conv_b     = (const float*)d_in[2];
    const float* ln_local_w = (const float*)d_in[3];
    const float* ln_local_b = (const float*)d_in[4];
    const float* ln_reg_w   = (const float*)d_in[5];
    const float* ln_reg_b   = (const float*)d_in[6];
    const float* in_proj_w  = (const float*)d_in[7];
    const float* in_proj_b  = (const float*)d_in[8];
    const float* out_proj_w = (const float*)d_in[9];
    const float* out_proj_b = (const float*)d_in[10];
    const float* ln_out_w   = (const float*)d_in[11];
    const float* ln_out_b   = (const float*)d_in[12];
    const float* mlp_w1     = (const float*)d_in[13];
    const float* mlp_b1     = (const float*)d_in[14];
    const float* mlp_w2     = (const float*)d_in[15];
    const float* mlp_b2     = (const float*)d_in[16];
    const void*  attn_mask  = (const void*)d_in[17];
    float* out = (float*)d_out;

    float *xp, *q, *op;
    bf16 *f, *ob, *hid, *m1, *Kb, *VbT, *wqkv, *wout, *wm1, *wm2;
    unsigned* mbp;
    cudaGetSymbolAddress((void**)&xp,  g_xp);
    cudaGetSymbolAddress((void**)&f,   g_f);
    cudaGetSymbolAddress((void**)&q,   g_q);
    cudaGetSymbolAddress((void**)&ob,  g_ob);
    cudaGetSymbolAddress((void**)&op,  g_op);
    cudaGetSymbolAddress((void**)&hid, g_hid);
    cudaGetSymbolAddress((void**)&m1,  g_m1);
    cudaGetSymbolAddress((void**)&mbp, g_mb);
    cudaGetSymbolAddress((void**)&Kb,  g_Kb);
    cudaGetSymbolAddress((void**)&VbT, g_VbT);
    cudaGetSymbolAddress((void**)&wqkv, g_wqkv);
    cudaGetSymbolAddress((void**)&wout, g_wout);
    cudaGetSymbolAddress((void**)&wm1,  g_wm1);
    cudaGetSymbolAddress((void**)&wm2,  g_wm2);

    // preamble (2 launches)
    k_pack_mask<<<(Stok * NW + 255) / 256, 256>>>(attn_mask, mbp);
    k_cvtw_all<<<(WTOT / 4 + 255) / 256, 256>>>(in_proj_w, out_proj_w, mlp_w1, mlp_w2);

    // conv (1x1), reading x[b][c][p] directly (fused transpose, tf32)
    k_conv<<<dim3(Cc / 64, (Bz * HW) / 128), 256>>>(x, conv_w, conv_b, xp, Bz * HW, Cc, Cc);

    // feats: LN local + pooled LN (bf16 out)
    k_ln<<<Bz * HW / 8, 256>>>(xp, HW, ln_local_w, ln_local_b, f, Stok);
    k_pool_ln<<<dim3(144, Bz), 256>>>(xp, ln_reg_w, ln_reg_b, f, 4, HW, 0);
    k_pool_ln<<<dim3(36,  Bz), 256>>>(xp, ln_reg_w, ln_reg_b, f, 8, HW + 144, 1);

    // qkv bf16 GEMM, split epilogue: Q -> g_q f32 (local only), K -> g_Kb, V -> g_VbT (transposed)
    k_bgemm<0, 1><<<dim3(768 / 64, (Bz * Stok + 127) / 128), 256>>>(
        f, wqkv, in_proj_b, nullptr, nullptr, q, Bz * Stok, 3 * Cc, Cc);

    // attention — BQ=128, 2 CTAs/SM; bf16 output
    k_attn<<<dim3(HW / 128, 8, Bz), 256>>>(q, Kb, VbT, mbp, ob);

    // out_proj (bf16 in, f32 out)
    k_bgemm<0, 0><<<dim3(Cc / 64, (Bz * HW) / 128), 256>>>(
        ob, wout, out_proj_b, nullptr, nullptr, op, Bz * HW, Cc, Cc);

    // ln_out on local tokens (bf16 out)
    k_ln<<<Bz * HW / 8, 256>>>(op, HW, ln_out_w, ln_out_b, hid, HW);

    // mlp: mlp1 bf16->bf16 with GELU; mlp2 fused transposed final store (+op residual +x)
    k_bgemm<1, 3><<<dim3(BOT / 64, (Bz * HW) / 128), 256>>>(
        hid, wm1, mlp_b1, nullptr, nullptr, m1, Bz * HW, BOT, Cc);
    k_bgemm<0, 4><<<dim3(Cc / 64, (Bz * HW) / 128), 256>>>(
        m1, wm2, mlp_b2, op, x, out, Bz * HW, Cc, BOT);
}

// round 16
// speedup vs baseline: 1.1039x; 1.0590x over previous
#include <cuda_runtime.h>
#include <cuda_bf16.h>
#include <math.h>

#define Bz   4
#define Cc   256
#define Hh   48
#define Ww   48
#define HW   2304
#define Stok 2484
#define NW   78      // ceil(S/32) mask words per row
#define KPAD 2496    // 39 * 64
#define BOT  64

typedef __nv_bfloat16 bf16;

// ---------------- scratch (device globals; zero-initialized, no allocs) ----------------
__device__ float g_xp [(size_t)Bz*HW*Cc];
__device__ bf16  g_f  [(size_t)Bz*Stok*Cc];    // LN features (bf16)
__device__ float g_q  [(size_t)Bz*HW*Cc];      // Q, local tokens only, f32
__device__ bf16  g_ob [(size_t)Bz*HW*Cc];      // attention out (bf16)
__device__ float g_op [(size_t)Bz*HW*Cc];
__device__ bf16  g_hid[(size_t)Bz*HW*Cc];      // ln_out (bf16)
__device__ bf16  g_m1 [(size_t)Bz*HW*BOT];     // gelu(mlp1) (bf16)
__device__ unsigned g_mb[(size_t)Stok*NW];
__device__ bf16 g_Kb [(size_t)Bz*8*KPAD*32];   // [b][h][key][32]
__device__ bf16 g_VbT[(size_t)Bz*8*32*KPAD];   // [b][h][32][key] (written directly by qkv)
__device__ bf16 g_wqkv[768*256];               // converted weights
__device__ bf16 g_wout[256*256];
__device__ bf16 g_wm1 [BOT*256];
__device__ bf16 g_wm2 [256*BOT];

// ---------------- small helpers ----------------
__device__ __forceinline__ void cpa16(void* dst, const void* src) {
    unsigned d = (unsigned)__cvta_generic_to_shared(dst);
    asm volatile("cp.async.cg.shared.global [%0], [%1], 16;" :: "r"(d), "l"(src));
}
__device__ __forceinline__ void cpa16z(void* dst, const void* src, int sz) {
    unsigned d = (unsigned)__cvta_generic_to_shared(dst);
    asm volatile("cp.async.cg.shared.global [%0], [%1], 16, %2;" :: "r"(d), "l"(src), "r"(sz));
}
__device__ __forceinline__ void cpa_commit() { asm volatile("cp.async.commit_group;"); }
__device__ __forceinline__ void cpa_wait0()  { asm volatile("cp.async.wait_group 0;"); }
__device__ __forceinline__ void cpa_wait1()  { asm volatile("cp.async.wait_group 1;"); }

__device__ __forceinline__ float ex2(float x) {    // guaranteed single MUFU.EX2
    float y;
    asm("ex2.approx.ftz.f32 %0, %1;" : "=f"(y) : "f"(x));
    return y;
}

__device__ __forceinline__ void mma_tf32(float c[4], const float a[4], float b0, float b1) {
    const unsigned* A = reinterpret_cast<const unsigned*>(a);
    unsigned B0 = __float_as_uint(b0), B1 = __float_as_uint(b1);
    asm volatile(
        "mma.sync.aligned.m16n8k8.row.col.f32.tf32.tf32.f32 "
        "{%0,%1,%2,%3},{%4,%5,%6,%7},{%8,%9},{%0,%1,%2,%3};"
        : "+f"(c[0]), "+f"(c[1]), "+f"(c[2]), "+f"(c[3])
        : "r"(A[0]), "r"(A[1]), "r"(A[2]), "r"(A[3]), "r"(B0), "r"(B1));
}
__device__ __forceinline__ void mma_bf16(float c[4], const unsigned a[4],
                                         unsigned b0, unsigned b1) {
    asm volatile(
        "mma.sync.aligned.m16n8k16.row.col.f32.bf16.bf16.f32 "
        "{%0,%1,%2,%3},{%4,%5,%6,%7},{%8,%9},{%0,%1,%2,%3};"
        : "+f"(c[0]), "+f"(c[1]), "+f"(c[2]), "+f"(c[3])
        : "r"(a[0]), "r"(a[1]), "r"(a[2]), "r"(a[3]), "r"(b0), "r"(b1));
}
__device__ __forceinline__ unsigned pkbf(float lo, float hi) {
    __nv_bfloat162 h = __float22bfloat162_rn(make_float2(lo, hi));
    return *reinterpret_cast<unsigned*>(&h);
}

// ---------------- merged preamble: mask pack (+probe) and weight conversion ----------------
#define WQKV_N (768*256)
#define WOUT_N (256*256)
#define WM1_N  (BOT*256)
#define WM2_N  (256*BOT)
#define WTOT   (WQKV_N + WOUT_N + WM1_N + WM2_N)
#define MASK_BLOCKS ((Stok * NW + 255) / 256)
#define CVT_BLOCKS  ((WTOT / 4 + 255) / 256)

__global__ void k_pre(const void* __restrict__ mv, unsigned* __restrict__ out,
                      const float* __restrict__ s0, const float* __restrict__ s1,
                      const float* __restrict__ s2, const float* __restrict__ s3)
{
    if (blockIdx.x < MASK_BLOCKS) {
        __shared__ int bad_i32, bad_f32;
        if (threadIdx.x == 0) { bad_i32 = 0; bad_f32 = 0; }
        __syncthreads();
        {
            const unsigned* m = (const unsigned*)mv;
            for (int i = threadIdx.x; i < Stok / 4; i += blockDim.x) {
                unsigned v = m[i];
                if (v != 0u && v != 1u)           bad_i32 = 1;   // benign race
                if (v != 0u && v != 0x3F800000u)  bad_f32 = 1;
            }
        }
        __syncthreads();
        int dt = (!bad_i32) ? 1 : ((!bad_f32) ? 2 : 0);

        int idx = blockIdx.x * blockDim.x + threadIdx.x;
        if (idx >= Stok * NW) return;
        int q = idx / NW, w = idx % NW;
        unsigned bits = 0;
        int c0 = w * 32;
        const unsigned char* mu = (const unsigned char*)mv;
        const int*           mi = (const int*)mv;
        const float*         mf = (const float*)mv;
        #pragma unroll 4
        for (int j = 0; j < 32; j++) {
            int c = c0 + j;
            bool blk;
            if (c >= Stok)      blk = true;
            else if (dt == 1)   blk = mi[(size_t)q * Stok + c] != 0;
            else if (dt == 2)   blk = mf[(size_t)q * Stok + c] != 0.0f;
            else                blk = mu[(size_t)q * Stok + c] != 0;
            if (blk) bits |= 1u << j;
        }
        out[idx] = bits;
    } else {
        int i = ((blockIdx.x - MASK_BLOCKS) * blockDim.x + threadIdx.x) * 4;
        const float* src; bf16* dst; int base;
        if (i < WQKV_N)                       { src = s0; dst = g_wqkv; base = 0; }
        else if (i < WQKV_N + WOUT_N)         { src = s1; dst = g_wout; base = WQKV_N; }
        else if (i < WQKV_N + WOUT_N + WM1_N) { src = s2; dst = g_wm1;  base = WQKV_N + WOUT_N; }
        else if (i < WTOT)                    { src = s3; dst = g_wm2;  base = WQKV_N + WOUT_N + WM1_N; }
        else return;
        int k = i - base;
        float4 v = *(const float4*)(src + k);
        *(uint2*)(dst + k) = make_uint2(pkbf(v.x, v.y), pkbf(v.z, v.w));
    }
}

// ---------------- tf32 mma GEMM for conv (fused transpose A) ----------------
__device__ __forceinline__ float gelu_exact(float v) {
    return 0.5f * v * (1.0f + erff(v * 0.70710678118654752f));
}

__global__ void __launch_bounds__(256) k_conv(
    const float* __restrict__ A, const float* __restrict__ W,
    const float* __restrict__ bias, float* __restrict__ C,
    int M, int N, int K)
{
    __shared__ __align__(16) float As[3][16 * 136];
    __shared__ __align__(16) float Bs[3][64 * 20];
    int tid = threadIdx.x;
    int warp = tid >> 5, lane = tid & 31;
    int g = lane >> 2, t4 = lane & 3;
    int m0 = blockIdx.y * 128, n0 = blockIdx.x * 64;
    int bb = m0 / HW, p0 = m0 % HW;

    auto issue = [&](int k0, int st) {
        #pragma unroll
        for (int r = 0; r < 2; r++) {
            int i = tid + r * 256;
            int kk = i >> 5, c = i & 31;
            const float* src = A + ((size_t)bb * Cc + k0 + kk) * HW + p0 + c * 4;
            cpa16(&As[st][kk * 136 + c * 4], src);
        }
        {
            int row = tid >> 2, c = tid & 3;
            cpa16(&Bs[st][row * 20 + c * 4], W + (size_t)(n0 + row) * K + k0 + c * 4);
        }
        cpa_commit();
    };

    float acc[8][4] = {};
    int nk = K >> 4;
    issue(0, 0);
    issue(16, 1);

    int st = 0;
    for (int ki = 0; ki < nk; ki++) {
        if (ki + 1 < nk) cpa_wait1(); else cpa_wait0();
        __syncthreads();
        if (ki + 2 < nk) {
            int nst = st + 2; if (nst >= 3) nst -= 3;
            issue((ki + 2) << 4, nst);
        }
        const float* as = As[st];
        const float* bs = Bs[st];
        if (++st == 3) st = 0;

        float a[2][4];
        #pragma unroll
        for (int ks = 0; ks < 2; ks++) {
            a[ks][0] = as[(ks * 8 + t4) * 136 + warp * 16 + g];
            a[ks][1] = as[(ks * 8 + t4) * 136 + warp * 16 + 8 + g];
            a[ks][2] = as[(ks * 8 + t4 + 4) * 136 + warp * 16 + g];
            a[ks][3] = as[(ks * 8 + t4 + 4) * 136 + warp * 16 + 8 + g];
        }
        #pragma unroll
        for (int n8 = 0; n8 < 8; n8++) {
            #pragma unroll
            for (int ks = 0; ks < 2; ks++) {
                float b0 = bs[(n8 * 8 + g) * 20 + ks * 8 + t4];
                float b1 = bs[(n8 * 8 + g) * 20 + ks * 8 + t4 + 4];
                mma_tf32(acc[n8], a[ks], b0, b1);
            }
        }
    }

    int gm0 = m0 + warp * 16 + g;
    int gm1 = gm0 + 8;
    #pragma unroll
    for (int n8 = 0; n8 < 8; n8++) {
        int col = n0 + n8 * 8 + 2 * t4;
        float2 bb2 = *(const float2*)(bias + col);
        *(float2*)(C + (size_t)gm0 * N + col) = make_float2(acc[n8][0] + bb2.x, acc[n8][1] + bb2.y);
        *(float2*)(C + (size_t)gm1 * N + col) = make_float2(acc[n8][2] + bb2.x, acc[n8][3] + bb2.y);
    }
}

// ---------------- bf16 mma GEMM, 3-stage cp.async pipeline ----------------
// MODE=0: f32 C. MODE=1: qkv split (Q->f32 compact C, K->g_Kb, V->g_VbT transposed).
// MODE=2: f32 C = acc + bias + D. MODE=3: bf16 C.
// MODE=4: transposed final store: out[b][c][p] = acc + bias + D[p][c] + X[b][c][p].
template<int ACT, int MODE>
__global__ void __launch_bounds__(256) k_bgemm(
    const bf16* __restrict__ A, const bf16* __restrict__ W,
    const float* __restrict__ bias, const float* __restrict__ D,
    const float* __restrict__ X, void* __restrict__ Cv, int M, int N, int K)
{
    __shared__ __align__(16) unsigned As[3][128 * 20];
    __shared__ __align__(16) unsigned Bs[3][64 * 20];
    int tid = threadIdx.x;
    int warp = tid >> 5, lane = tid & 31;
    int g = lane >> 2, t4 = lane & 3;
    int m0 = blockIdx.y * 128, n0 = blockIdx.x * 64;

    auto issue = [&](int k0, int st) {
        #pragma unroll
        for (int i = tid; i < 512; i += 256) {
            int row = i >> 2, c = i & 3;
            int gm = m0 + row;
            int ok = gm < M;
            const bf16* src = A + (size_t)(ok ? gm : 0) * K + k0 + c * 8;
            cpa16z(&As[st][row * 20 + c * 4], src, ok ? 16 : 0);
        }
        {
            int row = tid >> 2, c = tid & 3;
            cpa16(&Bs[st][row * 20 + c * 4], W + (size_t)(n0 + row) * K + k0 + c * 8);
        }
        cpa_commit();
    };

    float acc[8][4] = {};
    int nk = K >> 5;
    issue(0, 0);
    if (nk > 1) issue(32, 1);

    int st = 0;
    for (int ki = 0; ki < nk; ki++) {
        if (ki + 1 < nk) cpa_wait1(); else cpa_wait0();
        __syncthreads();
        if (ki + 2 < nk) {
            int nst = st + 2; if (nst >= 3) nst -= 3;
            issue((ki + 2) << 5, nst);
        }
        const unsigned* as = As[st];
        const unsigned* bs = Bs[st];
        if (++st == 3) st = 0;

        unsigned a[2][4];
        #pragma unroll
        for (int ks = 0; ks < 2; ks++) {
            a[ks][0] = as[(warp * 16 + g) * 20 + ks * 8 + t4];
            a[ks][1] = as[(warp * 16 + 8 + g) * 20 + ks * 8 + t4];
            a[ks][2] = as[(warp * 16 + g) * 20 + ks * 8 + t4 + 4];
            a[ks][3] = as[(warp * 16 + 8 + g) * 20 + ks * 8 + t4 + 4];
        }
        #pragma unroll
        for (int n8 = 0; n8 < 8; n8++) {
            #pragma unroll
            for (int ks = 0; ks < 2; ks++) {
                unsigned b0 = bs[(n8 * 8 + g) * 20 + ks * 8 + t4];
                unsigned b1 = bs[(n8 * 8 + g) * 20 + ks * 8 + t4 + 4];
                mma_bf16(acc[n8], a[ks], b0, b1);
            }
        }
    }

    int gm0 = m0 + warp * 16 + g;
    int gm1 = gm0 + 8;

    if (MODE == 1) {
        float* C = (float*)Cv;
        int region = n0 >> 8;    // 0=Q, 1=K, 2=V
        int b0i = gm0 / Stok, s0 = gm0 - b0i * Stok;
        int b1i = gm1 / Stok, s1 = gm1 - b1i * Stok;
        #pragma unroll
        for (int n8 = 0; n8 < 8; n8++) {
            int col = n0 + n8 * 8 + 2 * t4;
            float2 bb2 = *(const float2*)(bias + col);
            float v0 = acc[n8][0] + bb2.x, v1 = acc[n8][1] + bb2.y;
            float v2 = acc[n8][2] + bb2.x, v3 = acc[n8][3] + bb2.y;
            if (region == 0) {
                if (gm0 < M && s0 < HW)
                    *(float2*)(C + ((size_t)b0i * HW + s0) * 256 + col) = make_float2(v0, v1);
                if (gm1 < M && s1 < HW)
                    *(float2*)(C + ((size_t)b1i * HW + s1) * 256 + col) = make_float2(v2, v3);
            } else if (region == 1) {
                int dd = col & 31, hh = (col >> 5) & 7;
                if (gm0 < M)
                    *(unsigned*)(g_Kb + ((size_t)(b0i * 8 + hh) * KPAD + s0) * 32 + dd) = pkbf(v0, v1);
                if (gm1 < M)
                    *(unsigned*)(g_Kb + ((size_t)(b1i * 8 + hh) * KPAD + s1) * 32 + dd) = pkbf(v2, v3);
            } else {
                int dd = col & 31, hh = (col >> 5) & 7;
                if (gm0 < M) {
                    bf16* base = g_VbT + (size_t)(b0i * 8 + hh) * 32 * KPAD;
                    base[(size_t)dd * KPAD + s0]       = __float2bfloat16_rn(v0);
                    base[(size_t)(dd + 1) * KPAD + s0] = __float2bfloat16_rn(v1);
                }
                if (gm1 < M) {
                    bf16* base = g_VbT + (size_t)(b1i * 8 + hh) * 32 * KPAD;
                    base[(size_t)dd * KPAD + s1]       = __float2bfloat16_rn(v2);
                    base[(size_t)(dd + 1) * KPAD + s1] = __float2bfloat16_rn(v3);
                }
            }
        }
        return;
    }

    if (MODE == 4) {
        float* C = (float*)Cv;
        int b0i = gm0 / HW, p0 = gm0 - b0i * HW;
        int b1i = gm1 / HW, p1 = gm1 - b1i * HW;
        #pragma unroll
        for (int n8 = 0; n8 < 8; n8++) {
            int col = n0 + n8 * 8 + 2 * t4;
            float2 bb2 = *(const float2*)(bias + col);
            float2 d0 = *(const float2*)(D + (size_t)gm0 * N + col);
            float2 d1 = *(const float2*)(D + (size_t)gm1 * N + col);
            size_t i00 = ((size_t)b0i * Cc + col) * HW + p0;
            size_t i01 = ((size_t)b0i * Cc + col + 1) * HW + p0;
            size_t i10 = ((size_t)b1i * Cc + col) * HW + p1;
            size_t i11 = ((size_t)b1i * Cc + col + 1) * HW + p1;
            C[i00] = acc[n8][0] + bb2.x + d0.x + X[i00];
            C[i01] = acc[n8][1] + bb2.y + d0.y + X[i01];
            C[i10] = acc[n8][2] + bb2.x + d1.x + X[i10];
            C[i11] = acc[n8][3] + bb2.y + d1.y + X[i11];
        }
        return;
    }

    #pragma unroll
    for (int n8 = 0; n8 < 8; n8++) {
        int col = n0 + n8 * 8 + 2 * t4;
        float2 bb2 = *(const float2*)(bias + col);
        float v0 = acc[n8][0] + bb2.x, v1 = acc[n8][1] + bb2.y;
        float v2 = acc[n8][2] + bb2.x, v3 = acc[n8][3] + bb2.y;
        if (ACT == 1) {
            v0 = gelu_exact(v0); v1 = gelu_exact(v1);
            v2 = gelu_exact(v2); v3 = gelu_exact(v3);
        }
        if (MODE == 2) {
            if (gm0 < M) {
                float2 d0 = *(const float2*)(D + (size_t)gm0 * N + col);
                v0 += d0.x; v1 += d0.y;
            }
            if (gm1 < M) {
                float2 d1 = *(const float2*)(D + (size_t)gm1 * N + col);
                v2 += d1.x; v3 += d1.y;
            }
        }
        if (MODE == 3) {
            bf16* C = (bf16*)Cv;
            if (gm0 < M) *(unsigned*)(C + (size_t)gm0 * N + col) = pkbf(v0, v1);
            if (gm1 < M) *(unsigned*)(C + (size_t)gm1 * N + col) = pkbf(v2, v3);
        } else {
            float* C = (float*)Cv;
            if (gm0 < M) *(float2*)(C + (size_t)gm0 * N + col) = make_float2(v0, v1);
            if (gm1 < M) *(float2*)(C + (size_t)gm1 * N + col) = make_float2(v2, v3);
        }
    }
}

// ---------------- layernorm: 2 rows per warp (interleaved reduce chains) ----------------
__global__ void k_ln(const float* __restrict__ in, int inTok,
                     const float* __restrict__ w, const float* __restrict__ bv,
                     bf16* __restrict__ out, int outTok)
{
    int wid = blockIdx.x * 8 + (threadIdx.x >> 5);
    int lane = threadIdx.x & 31;
    int rowA = wid * 2, rowB = rowA + 1;
    int bA = rowA / HW, pA = rowA % HW;
    int bB = rowB / HW, pB = rowB % HW;
    const float* srcA = in + ((size_t)bA * inTok + pA) * Cc;
    const float* srcB = in + ((size_t)bB * inTok + pB) * Cc;
    float4 a0 = *(const float4*)(srcA + lane * 4);
    float4 a1 = *(const float4*)(srcA + 128 + lane * 4);
    float4 b0 = *(const float4*)(srcB + lane * 4);
    float4 b1 = *(const float4*)(srcB + 128 + lane * 4);
    float sA = a0.x + a0.y + a0.z + a0.w + a1.x + a1.y + a1.z + a1.w;
    float sB = b0.x + b0.y + b0.z + b0.w + b1.x + b1.y + b1.z + b1.w;
    #pragma unroll
    for (int o = 16; o > 0; o >>= 1) {
        sA += __shfl_xor_sync(0xffffffffu, sA, o);
        sB += __shfl_xor_sync(0xffffffffu, sB, o);
    }
    float mA = sA * (1.0f / 256.0f), mB = sB * (1.0f / 256.0f);
    float dA[8] = {a0.x-mA, a0.y-mA, a0.z-mA, a0.w-mA, a1.x-mA, a1.y-mA, a1.z-mA, a1.w-mA};
    float dB[8] = {b0.x-mB, b0.y-mB, b0.z-mB, b0.w-mB, b1.x-mB, b1.y-mB, b1.z-mB, b1.w-mB};
    float vA = 0.f, vB = 0.f;
    #pragma unroll
    for (int i = 0; i < 8; i++) { vA += dA[i]*dA[i]; vB += dB[i]*dB[i]; }
    #pragma unroll
    for (int o = 16; o > 0; o >>= 1) {
        vA += __shfl_xor_sync(0xffffffffu, vA, o);
        vB += __shfl_xor_sync(0xffffffffu, vB, o);
    }
    float rA = rsqrtf(vA * (1.0f / 256.0f) + 1e-5f);
    float rB = rsqrtf(vB * (1.0f / 256.0f) + 1e-5f);
    float4 w0 = *(const float4*)(w + lane * 4);
    float4 w1 = *(const float4*)(w + 128 + lane * 4);
    float4 c0 = *(const float4*)(bv + lane * 4);
    float4 c1 = *(const float4*)(bv + 128 + lane * 4);
    float wr[8] = {w0.x, w0.y, w0.z, w0.w, w1.x, w1.y, w1.z, w1.w};
    float cr[8] = {c0.x, c0.y, c0.z, c0.w, c1.x, c1.y, c1.z, c1.w};
    bf16* dstA = out + ((size_t)bA * outTok + pA) * Cc;
    bf16* dstB = out + ((size_t)bB * outTok + pB) * Cc;
    uint2 oA0 = make_uint2(pkbf(dA[0]*rA*wr[0]+cr[0], dA[1]*rA*wr[1]+cr[1]),
                           pkbf(dA[2]*rA*wr[2]+cr[2], dA[3]*rA*wr[3]+cr[3]));
    uint2 oA1 = make_uint2(pkbf(dA[4]*rA*wr[4]+cr[4], dA[5]*rA*wr[5]+cr[5]),
                           pkbf(dA[6]*rA*wr[6]+cr[6], dA[7]*rA*wr[7]+cr[7]));
    uint2 oB0 = make_uint2(pkbf(dB[0]*rB*wr[0]+cr[0], dB[1]*rB*wr[1]+cr[1]),
                           pkbf(dB[2]*rB*wr[2]+cr[2], dB[3]*rB*wr[3]+cr[3]));
    uint2 oB1 = make_uint2(pkbf(dB[4]*rB*wr[4]+cr[4], dB[5]*rB*wr[5]+cr[5]),
                           pkbf(dB[6]*rB*wr[6]+cr[6], dB[7]*rB*wr[7]+cr[7]));
    *(uint2*)(dstA + lane * 4) = oA0;
    *(uint2*)(dstA + 128 + lane * 4) = oA1;
    *(uint2*)(dstB + lane * 4) = oB0;
    *(uint2*)(dstB + 128 + lane * 4) = oB1;
}

// ---------------- pool (ps x ps mean) + layernorm (bf16 output) ----------------
__global__ void k_pool_ln(const float* __restrict__ xp,
                          const float* __restrict__ w, const float* __restrict__ bv,
                          bf16* __restrict__ f, int ps, int off, int reg)
{
    int b = blockIdx.y;
    int t = blockIdx.x;
    int gw = Ww / ps;
    int bh = t / gw, bw = t % gw;
    int c = threadIdx.x;
    float s = 0.f;
    for (int i = 0; i < ps; i++) {
        int prow = (bh * ps + i) * Ww + bw * ps;
        const float* base = xp + ((size_t)b * HW + prow) * Cc + c;
        for (int j = 0; j < ps; j++) s += base[(size_t)j * Cc];
    }
    float v = s / (float)(ps * ps);
    __shared__ float sb[8];
    float ss = v;
    #pragma unroll
    for (int o = 16; o > 0; o >>= 1) ss += __shfl_xor_sync(0xffffffffu, ss, o);
    if ((c & 31) == 0) sb[c >> 5] = ss;
    __syncthreads();
    float tot = 0.f;
    #pragma unroll
    for (int i = 0; i < 8; i++) tot += sb[i];
    float mean = tot * (1.0f / 256.0f);
    __syncthreads();
    float d = v - mean;
    float s2 = d * d;
    #pragma unroll
    for (int o = 16; o > 0; o >>= 1) s2 += __shfl_xor_sync(0xffffffffu, s2, o);
    if ((c & 31) == 0) sb[c >> 5] = s2;
    __syncthreads();
    float tot2 = 0.f;
    #pragma unroll
    for (int i = 0; i < 8; i++) tot2 += sb[i];
    float rs = rsqrtf(tot2 * (1.0f / 256.0f) + 1e-5f);
    f[((size_t)b * Stok + off + t) * Cc + c] =
        __float2bfloat16_rn(d * rs * w[reg * Cc + c] + bv[reg * Cc + c]);
}

// ---------------- bf16 mma flash attention, BQ=128, 2 CTAs/SM, 3-stage ----------------
#define KV_TILES 39

__global__ void __launch_bounds__(256, 2) k_attn(const float* __restrict__ qv,
                                                 const bf16* __restrict__ Kb,
                                                 const bf16* __restrict__ VbT,
                                                 const unsigned* __restrict__ mb,
                                                 bf16* __restrict__ out)
{
    __shared__ __align__(16) unsigned char KsB[3][64 * 80];
    __shared__ __align__(16) unsigned char VsB[3][32 * 144];
    __shared__ unsigned Msm[3][256];

    int tid  = threadIdx.x;
    int warp = tid >> 5, lane = tid & 31;
    int g = lane >> 2, t4 = lane & 3;
    int q0 = blockIdx.x * 128, h = blockIdx.y, b = blockIdx.z;
    int bh = b * 8 + h;

    const bf16* Kg = Kb  + (size_t)bh * KPAD * 32;
    const bf16* Vg = VbT + (size_t)bh * 32 * KPAD;
    const float* qb = qv + ((size_t)b * HW) * 256 + h * 32;

    const float SC = 0.17677669529663687f * 1.4426950408889634f;  // 1/sqrt(32)*log2e
    int r0 = q0 + warp * 16 + g;
    int r1 = r0 + 8;

    unsigned qa[2][4];
    #pragma unroll
    for (int ks = 0; ks < 2; ks++) {
        #pragma unroll
        for (int half = 0; half < 2; half++) {
            int kc = ks * 16 + half * 8 + 2 * t4;
            float2 u0 = *(const float2*)(qb + (size_t)r0 * 256 + kc);
            float2 u1 = *(const float2*)(qb + (size_t)r1 * 256 + kc);
            qa[ks][half * 2 + 0] = pkbf(u0.x * SC, u0.y * SC);
            qa[ks][half * 2 + 1] = pkbf(u1.x * SC, u1.y * SC);
        }
    }

    auto issue = [&](int kt) {
        int k0 = kt * 64;
        int st = kt % 3;
        {
            int row = tid >> 2, c = tid & 3;
            cpa16(&KsB[st][row * 80 + c * 16], Kg + (size_t)(k0 + row) * 32 + c * 8);
        }
        {
            int d = tid >> 3, c = tid & 7;
            cpa16(&VsB[st][d * 144 + c * 16], Vg + (size_t)d * KPAD + k0 + c * 8);
        }
        cpa_commit();
        if (tid < 128) {
            int row = tid, gq = q0 + row;
            Msm[st][row * 2]     = mb[(size_t)gq * NW + kt * 2];
            Msm[st][row * 2 + 1] = mb[(size_t)gq * NW + kt * 2 + 1];
        }
    };

    float l0 = 0.f, l1 = 0.f;
    float o[4][4] = {};

    issue(0);
    issue(1);
    for (int kt = 0; kt < KV_TILES; kt++) {
        if (kt + 1 < KV_TILES) cpa_wait1(); else cpa_wait0();
        __syncthreads();
        if (kt + 2 < KV_TILES) issue(kt + 2);

        int cur = kt % 3;
        const unsigned* Kw = (const unsigned*)KsB[cur];
        const unsigned* Vw = (const unsigned*)VsB[cur];

        unsigned w00 = Msm[cur][(warp * 16 + g) * 2 + 0];
        unsigned w01 = Msm[cur][(warp * 16 + g) * 2 + 1];
        unsigned w10 = Msm[cur][(warp * 16 + 8 + g) * 2 + 0];
        unsigned w11 = Msm[cur][(warp * 16 + 8 + g) * 2 + 1];

        float rs0 = 0.f, rs1 = 0.f;

        #pragma unroll
        for (int j = 0; j < 4; j++) {
            int n8a = 2 * j, n8b = 2 * j + 1;
            float s0[4] = {0.f, 0.f, 0.f, 0.f};
            float s1[4] = {0.f, 0.f, 0.f, 0.f};
            #pragma unroll
            for (int ks = 0; ks < 2; ks++) {
                mma_bf16(s0, qa[ks], Kw[(n8a * 8 + g) * 20 + ks * 8 + t4],
                                     Kw[(n8a * 8 + g) * 20 + ks * 8 + t4 + 4]);
                mma_bf16(s1, qa[ks], Kw[(n8b * 8 + g) * 20 + ks * 8 + t4],
                                     Kw[(n8b * 8 + g) * 20 + ks * 8 + t4 + 4]);
            }
            unsigned mr0 = (j < 2) ? w00 : w01;
            unsigned mr1 = (j < 2) ? w10 : w11;
            int sha = (n8a * 8 + 2 * t4) & 31;
            int shb = (n8b * 8 + 2 * t4) & 31;
            if ((mr0 >> sha) & 1u)        s0[0] = -1.0e9f;
            if ((mr0 >> (sha + 1)) & 1u)  s0[1] = -1.0e9f;
            if ((mr1 >> sha) & 1u)        s0[2] = -1.0e9f;
            if ((mr1 >> (sha + 1)) & 1u)  s0[3] = -1.0e9f;
            if ((mr0 >> shb) & 1u)        s1[0] = -1.0e9f;
            if ((mr0 >> (shb + 1)) & 1u)  s1[1] = -1.0e9f;
            if ((mr1 >> shb) & 1u)        s1[2] = -1.0e9f;
            if ((mr1 >> (shb + 1)) & 1u)  s1[3] = -1.0e9f;
            s0[0] = ex2(s0[0]); s0[1] = ex2(s0[1]);
            s0[2] = ex2(s0[2]); s0[3] = ex2(s0[3]);
            s1[0] = ex2(s1[0]); s1[1] = ex2(s1[1]);
            s1[2] = ex2(s1[2]); s1[3] = ex2(s1[3]);
            rs0 += s0[0] + s0[1] + s1[0] + s1[1];
            rs1 += s0[2] + s0[3] + s1[2] + s1[3];
            unsigned paj[4];
            paj[0] = pkbf(s0[0], s0[1]);
            paj[1] = pkbf(s0[2], s0[3]);
            paj[2] = pkbf(s1[0], s1[1]);
            paj[3] = pkbf(s1[2], s1[3]);
            #pragma unroll
            for (int d8 = 0; d8 < 4; d8++) {
                mma_bf16(o[d8], paj, Vw[(d8 * 8 + g) * 36 + j * 8 + t4],
                                     Vw[(d8 * 8 + g) * 36 + j * 8 + t4 + 4]);
            }
        }
        l0 += rs0;
        l1 += rs1;
    }

    l0 += __shfl_xor_sync(0xffffffffu, l0, 1);
    l0 += __shfl_xor_sync(0xffffffffu, l0, 2);
    l1 += __shfl_xor_sync(0xffffffffu, l1, 1);
    l1 += __shfl_xor_sync(0xffffffffu, l1, 2);
    float inv0 = 1.0f / l0, inv1 = 1.0f / l1;
    #pragma unroll
    for (int d8 = 0; d8 < 4; d8++) {
        int dc = h * 32 + d8 * 8 + 2 * t4;
        *(unsigned*)(out + ((size_t)b * HW + r0) * 256 + dc) =
            pkbf(o[d8][0] * inv0, o[d8][1] * inv0);
        *(unsigned*)(out + ((size_t)b * HW + r1) * 256 + dc) =
            pkbf(o[d8][2] * inv1, o[d8][3] * inv1);
    }
}

// ---------------- launch ----------------
extern "C" void kernel_launch(void* const* d_in, const int* in_sizes, int n_in,
                              void* d_out, int out_size)
{
    const float* x          = (const float*)d_in[0];
    const float* conv_w     = (const float*)d_in[1];
    const float* conv_b     = (const float*)d_in[2];
    const float* ln_local_w = (const float*)d_in[3];
    const float* ln_local_b = (const float*)d_in[4];
    const float* ln_reg_w   = (const float*)d_in[5];
    const float* ln_reg_b   = (const float*)d_in[6];
    const float* in_proj_w  = (const float*)d_in[7];
    const float* in_proj_b  = (const float*)d_in[8];
    const float* out_proj_w = (const float*)d_in[9];
    const float* out_proj_b = (const float*)d_in[10];
    const float* ln_out_w   = (const float*)d_in[11];
    const float* ln_out_b   = (const float*)d_in[12];
    const float* mlp_w1     = (const float*)d_in[13];
    const float* mlp_b1     = (const float*)d_in[14];
    const float* mlp_w2     = (const float*)d_in[15];
    const float* mlp_b2     = (const float*)d_in[16];
    const void*  attn_mask  = (const void*)d_in[17];
    float* out = (float*)d_out;

    float *xp, *q, *op;
    bf16 *f, *ob, *hid, *m1, *Kb, *VbT, *wqkv, *wout, *wm1, *wm2;
    unsigned* mbp;
    cudaGetSymbolAddress((void**)&xp,  g_xp);
    cudaGetSymbolAddress((void**)&f,   g_f);
    cudaGetSymbolAddress((void**)&q,   g_q);
    cudaGetSymbolAddress((void**)&ob,  g_ob);
    cudaGetSymbolAddress((void**)&op,  g_op);
    cudaGetSymbolAddress((void**)&hid, g_hid);
    cudaGetSymbolAddress((void**)&m1,  g_m1);
    cudaGetSymbolAddress((void**)&mbp, g_mb);
    cudaGetSymbolAddress((void**)&Kb,  g_Kb);
    cudaGetSymbolAddress((void**)&VbT, g_VbT);
    cudaGetSymbolAddress((void**)&wqkv, g_wqkv);
    cudaGetSymbolAddress((void**)&wout, g_wout);
    cudaGetSymbolAddress((void**)&wm1,  g_wm1);
    cudaGetSymbolAddress((void**)&wm2,  g_wm2);

    // merged preamble (1 launch): mask pack (+probe) in first blocks, weight cvt after
    k_pre<<<MASK_BLOCKS + CVT_BLOCKS, 256>>>(attn_mask, mbp,
                                             in_proj_w, out_proj_w, mlp_w1, mlp_w2);

    // conv (1x1), reading x[b][c][p] directly (fused transpose, tf32)
    k_conv<<<dim3(Cc / 64, (Bz * HW) / 128), 256>>>(x, conv_w, conv_b, xp, Bz * HW, Cc, Cc);

    // feats: LN local + pooled LN (bf16 out)
    k_ln<<<Bz * HW / 16, 256>>>(xp, HW, ln_local_w, ln_local_b, f, Stok);
    k_pool_ln<<<dim3(144, Bz), 256>>>(xp, ln_reg_w, ln_reg_b, f, 4, HW, 0);
    k_pool_ln<<<dim3(36,  Bz), 256>>>(xp, ln_reg_w, ln_reg_b, f, 8, HW + 144, 1);

    // qkv bf16 GEMM, split epilogue: Q -> g_q f32 (local only), K -> g_Kb, V -> g_VbT (transposed)
    k_bgemm<0, 1><<<dim3(768 / 64, (Bz * Stok + 127) / 128), 256>>>(
        f, wqkv, in_proj_b, nullptr, nullptr, q, Bz * Stok, 3 * Cc, Cc);

    // attention — BQ=128, 2 CTAs/SM; bf16 output
    k_attn<<<dim3(HW / 128, 8, Bz), 256>>>(q, Kb, VbT, mbp, ob);

    // out_proj (bf16 in, f32 out)
    k_bgemm<0, 0><<<dim3(Cc / 64, (Bz * HW) / 128), 256>>>(
        ob, wout, out_proj_b, nullptr, nullptr, op, Bz * HW, Cc, Cc);

    // ln_out on local tokens (bf16 out)
    k_ln<<<Bz * HW / 16, 256>>>(op, HW, ln_out_w, ln_out_b, hid, HW);

    // mlp: mlp1 bf16->bf16 with GELU; mlp2 fused transposed final store (+op residual +x)
    k_bgemm<1, 3><<<dim3(BOT / 64, (Bz * HW) / 128), 256>>>(
        hid, wm1, mlp_b1, nullptr, nullptr, m1, Bz * HW, BOT, Cc);
    k_bgemm<0, 4><<<dim3(Cc / 64, (Bz * HW) / 128), 256>>>(
        m1, wm2, mlp_b2, op, x, out, Bz * HW, Cc, BOT);
}

// round 17
// speedup vs baseline: 1.1857x; 1.0741x over previous
#include <cuda_runtime.h>
#include <cuda_bf16.h>
#include <math.h>

#define Bz   4
#define Cc   256
#define Hh   48
#define Ww   48
#define HW   2304
#define Stok 2484
#define NW   78      // ceil(S/32) mask words per row
#define KPAD 2496    // 39 * 64
#define BOT  64

typedef __nv_bfloat16 bf16;

// ---------------- scratch (device globals; zero-initialized, no allocs) ----------------
__device__ float g_xp [(size_t)Bz*HW*Cc];
__device__ bf16  g_f  [(size_t)Bz*Stok*Cc];    // LN features (bf16)
__device__ bf16  g_qb [(size_t)Bz*HW*Cc];      // Q, local only, pre-scaled bf16
__device__ bf16  g_ob [(size_t)Bz*HW*Cc];      // attention out (bf16)
__device__ float g_op [(size_t)Bz*HW*Cc];
__device__ bf16  g_hid[(size_t)Bz*HW*Cc];      // ln_out (bf16)
__device__ bf16  g_m1 [(size_t)Bz*HW*BOT];     // gelu(mlp1) (bf16)
__device__ unsigned g_mb[(size_t)Stok*NW];
__device__ bf16 g_Kb [(size_t)Bz*8*KPAD*32];   // [b][h][key][32], pair-permuted rows
__device__ bf16 g_VbT[(size_t)Bz*8*32*KPAD];   // [b][h][32][key], per-tile key-permuted
__device__ bf16 g_wqkv[768*256];               // converted weights
__device__ bf16 g_wout[256*256];
__device__ bf16 g_wm1 [BOT*256];
__device__ bf16 g_wm2 [256*BOT];

// ---------------- small helpers ----------------
__device__ __forceinline__ void cpa16(void* dst, const void* src) {
    unsigned d = (unsigned)__cvta_generic_to_shared(dst);
    asm volatile("cp.async.cg.shared.global [%0], [%1], 16;" :: "r"(d), "l"(src));
}
__device__ __forceinline__ void cpa16z(void* dst, const void* src, int sz) {
    unsigned d = (unsigned)__cvta_generic_to_shared(dst);
    asm volatile("cp.async.cg.shared.global [%0], [%1], 16, %2;" :: "r"(d), "l"(src), "r"(sz));
}
__device__ __forceinline__ void cpa_commit() { asm volatile("cp.async.commit_group;"); }
__device__ __forceinline__ void cpa_wait0()  { asm volatile("cp.async.wait_group 0;"); }
__device__ __forceinline__ void cpa_wait1()  { asm volatile("cp.async.wait_group 1;"); }

__device__ __forceinline__ float ex2(float x) {    // single MUFU.EX2
    float y;
    asm("ex2.approx.ftz.f32 %0, %1;" : "=f"(y) : "f"(x));
    return y;
}

__device__ __forceinline__ void mma_tf32(float c[4], const float a[4], float b0, float b1) {
    const unsigned* A = reinterpret_cast<const unsigned*>(a);
    unsigned B0 = __float_as_uint(b0), B1 = __float_as_uint(b1);
    asm volatile(
        "mma.sync.aligned.m16n8k8.row.col.f32.tf32.tf32.f32 "
        "{%0,%1,%2,%3},{%4,%5,%6,%7},{%8,%9},{%0,%1,%2,%3};"
        : "+f"(c[0]), "+f"(c[1]), "+f"(c[2]), "+f"(c[3])
        : "r"(A[0]), "r"(A[1]), "r"(A[2]), "r"(A[3]), "r"(B0), "r"(B1));
}
__device__ __forceinline__ void mma_bf16(float c[4], const unsigned a[4],
                                         unsigned b0, unsigned b1) {
    asm volatile(
        "mma.sync.aligned.m16n8k16.row.col.f32.bf16.bf16.f32 "
        "{%0,%1,%2,%3},{%4,%5,%6,%7},{%8,%9},{%0,%1,%2,%3};"
        : "+f"(c[0]), "+f"(c[1]), "+f"(c[2]), "+f"(c[3])
        : "r"(a[0]), "r"(a[1]), "r"(a[2]), "r"(a[3]), "r"(b0), "r"(b1));
}
__device__ __forceinline__ unsigned pkbf(float lo, float hi) {
    __nv_bfloat162 h = __float22bfloat162_rn(make_float2(lo, hi));
    return *reinterpret_cast<unsigned*>(&h);
}

// V per-tile key permutation: pair q (0..31 within 64-key tile) -> q'
__device__ __forceinline__ int vperm(int s) {
    int kk = s & 63, base = s & ~63;
    int q = kk >> 1, par = kk & 1;
    int r = q & 7;
    int qp = (q & 0x18) + 2 * (r & 3) + (r >> 2);
    return base + qp * 2 + par;
}

// ---------------- merged preamble: mask pack (+probe) and weight conversion ----------------
#define WQKV_N (768*256)
#define WOUT_N (256*256)
#define WM1_N  (BOT*256)
#define WM2_N  (256*BOT)
#define WTOT   (WQKV_N + WOUT_N + WM1_N + WM2_N)
#define MASK_BLOCKS ((Stok * NW + 255) / 256)
#define CVT_BLOCKS  ((WTOT / 4 + 255) / 256)

__global__ void k_pre(const void* __restrict__ mv, unsigned* __restrict__ out,
                      const float* __restrict__ s0, const float* __restrict__ s1,
                      const float* __restrict__ s2, const float* __restrict__ s3)
{
    if (blockIdx.x < MASK_BLOCKS) {
        __shared__ int bad_i32, bad_f32;
        if (threadIdx.x == 0) { bad_i32 = 0; bad_f32 = 0; }
        __syncthreads();
        {
            const unsigned* m = (const unsigned*)mv;
            for (int i = threadIdx.x; i < Stok / 4; i += blockDim.x) {
                unsigned v = m[i];
                if (v != 0u && v != 1u)           bad_i32 = 1;   // benign race
                if (v != 0u && v != 0x3F800000u)  bad_f32 = 1;
            }
        }
        __syncthreads();
        int dt = (!bad_i32) ? 1 : ((!bad_f32) ? 2 : 0);

        int idx = blockIdx.x * blockDim.x + threadIdx.x;
        if (idx >= Stok * NW) return;
        int q = idx / NW, w = idx % NW;
        unsigned bits = 0;
        int c0 = w * 32;
        const unsigned char* mu = (const unsigned char*)mv;
        const int*           mi = (const int*)mv;
        const float*         mf = (const float*)mv;
        #pragma unroll 4
        for (int j = 0; j < 32; j++) {
            int c = c0 + j;
            bool blk;
            if (c >= Stok)      blk = true;
            else if (dt == 1)   blk = mi[(size_t)q * Stok + c] != 0;
            else if (dt == 2)   blk = mf[(size_t)q * Stok + c] != 0.0f;
            else                blk = mu[(size_t)q * Stok + c] != 0;
            if (blk) bits |= 1u << j;
        }
        out[idx] = bits;
    } else {
        int i = ((blockIdx.x - MASK_BLOCKS) * blockDim.x + threadIdx.x) * 4;
        const float* src; bf16* dst; int base;
        if (i < WQKV_N)                       { src = s0; dst = g_wqkv; base = 0; }
        else if (i < WQKV_N + WOUT_N)         { src = s1; dst = g_wout; base = WQKV_N; }
        else if (i < WQKV_N + WOUT_N + WM1_N) { src = s2; dst = g_wm1;  base = WQKV_N + WOUT_N; }
        else if (i < WTOT)                    { src = s3; dst = g_wm2;  base = WQKV_N + WOUT_N + WM1_N; }
        else return;
        int k = i - base;
        float4 v = *(const float4*)(src + k);
        *(uint2*)(dst + k) = make_uint2(pkbf(v.x, v.y), pkbf(v.z, v.w));
    }
}

// ---------------- tf32 mma GEMM for conv (fused transpose A) ----------------
__device__ __forceinline__ float gelu_exact(float v) {
    return 0.5f * v * (1.0f + erff(v * 0.70710678118654752f));
}

__global__ void __launch_bounds__(256) k_conv(
    const float* __restrict__ A, const float* __restrict__ W,
    const float* __restrict__ bias, float* __restrict__ C,
    int M, int N, int K)
{
    __shared__ __align__(16) float As[3][16 * 136];
    __shared__ __align__(16) float Bs[3][64 * 20];
    int tid = threadIdx.x;
    int warp = tid >> 5, lane = tid & 31;
    int g = lane >> 2, t4 = lane & 3;
    int m0 = blockIdx.y * 128, n0 = blockIdx.x * 64;
    int bb = m0 / HW, p0 = m0 % HW;

    auto issue = [&](int k0, int st) {
        #pragma unroll
        for (int r = 0; r < 2; r++) {
            int i = tid + r * 256;
            int kk = i >> 5, c = i & 31;
            const float* src = A + ((size_t)bb * Cc + k0 + kk) * HW + p0 + c * 4;
            cpa16(&As[st][kk * 136 + c * 4], src);
        }
        {
            int row = tid >> 2, c = tid & 3;
            cpa16(&Bs[st][row * 20 + c * 4], W + (size_t)(n0 + row) * K + k0 + c * 4);
        }
        cpa_commit();
    };

    float acc[8][4] = {};
    int nk = K >> 4;
    issue(0, 0);
    issue(16, 1);

    int st = 0;
    for (int ki = 0; ki < nk; ki++) {
        if (ki + 1 < nk) cpa_wait1(); else cpa_wait0();
        __syncthreads();
        if (ki + 2 < nk) {
            int nst = st + 2; if (nst >= 3) nst -= 3;
            issue((ki + 2) << 4, nst);
        }
        const float* as = As[st];
        const float* bs = Bs[st];
        if (++st == 3) st = 0;

        float a[2][4];
        #pragma unroll
        for (int ks = 0; ks < 2; ks++) {
            a[ks][0] = as[(ks * 8 + t4) * 136 + warp * 16 + g];
            a[ks][1] = as[(ks * 8 + t4) * 136 + warp * 16 + 8 + g];
            a[ks][2] = as[(ks * 8 + t4 + 4) * 136 + warp * 16 + g];
            a[ks][3] = as[(ks * 8 + t4 + 4) * 136 + warp * 16 + 8 + g];
        }
        #pragma unroll
        for (int n8 = 0; n8 < 8; n8++) {
            #pragma unroll
            for (int ks = 0; ks < 2; ks++) {
                float b0 = bs[(n8 * 8 + g) * 20 + ks * 8 + t4];
                float b1 = bs[(n8 * 8 + g) * 20 + ks * 8 + t4 + 4];
                mma_tf32(acc[n8], a[ks], b0, b1);
            }
        }
    }

    int gm0 = m0 + warp * 16 + g;
    int gm1 = gm0 + 8;
    #pragma unroll
    for (int n8 = 0; n8 < 8; n8++) {
        int col = n0 + n8 * 8 + 2 * t4;
        float2 bb2 = *(const float2*)(bias + col);
        *(float2*)(C + (size_t)gm0 * N + col) = make_float2(acc[n8][0] + bb2.x, acc[n8][1] + bb2.y);
        *(float2*)(C + (size_t)gm1 * N + col) = make_float2(acc[n8][2] + bb2.x, acc[n8][3] + bb2.y);
    }
}

// ---------------- bf16 mma GEMM, 3-stage cp.async pipeline ----------------
// MODE=0: f32 C. MODE=1: qkv split (Q->bf16 pre-scaled, K->g_Kb permuted, V->g_VbT permuted).
// MODE=2: f32 C = acc + bias + D. MODE=3: bf16 C.
// MODE=4: transposed final store: out[b][c][p] = acc + bias + D[p][c] + X[b][c][p].
template<int ACT, int MODE>
__global__ void __launch_bounds__(256) k_bgemm(
    const bf16* __restrict__ A, const bf16* __restrict__ W,
    const float* __restrict__ bias, const float* __restrict__ D,
    const float* __restrict__ X, void* __restrict__ Cv, int M, int N, int K)
{
    __shared__ __align__(16) unsigned As[3][128 * 20];
    __shared__ __align__(16) unsigned Bs[3][64 * 20];
    int tid = threadIdx.x;
    int warp = tid >> 5, lane = tid & 31;
    int g = lane >> 2, t4 = lane & 3;
    int m0 = blockIdx.y * 128, n0 = blockIdx.x * 64;

    auto issue = [&](int k0, int st) {
        #pragma unroll
        for (int i = tid; i < 512; i += 256) {
            int row = i >> 2, c = i & 3;
            int gm = m0 + row;
            int ok = gm < M;
            const bf16* src = A + (size_t)(ok ? gm : 0) * K + k0 + c * 8;
            cpa16z(&As[st][row * 20 + c * 4], src, ok ? 16 : 0);
        }
        {
            int row = tid >> 2, c = tid & 3;
            cpa16(&Bs[st][row * 20 + c * 4], W + (size_t)(n0 + row) * K + k0 + c * 8);
        }
        cpa_commit();
    };

    float acc[8][4] = {};
    int nk = K >> 5;
    issue(0, 0);
    if (nk > 1) issue(32, 1);

    int st = 0;
    for (int ki = 0; ki < nk; ki++) {
        if (ki + 1 < nk) cpa_wait1(); else cpa_wait0();
        __syncthreads();
        if (ki + 2 < nk) {
            int nst = st + 2; if (nst >= 3) nst -= 3;
            issue((ki + 2) << 5, nst);
        }
        const unsigned* as = As[st];
        const unsigned* bs = Bs[st];
        if (++st == 3) st = 0;

        unsigned a[2][4];
        #pragma unroll
        for (int ks = 0; ks < 2; ks++) {
            a[ks][0] = as[(warp * 16 + g) * 20 + ks * 8 + t4];
            a[ks][1] = as[(warp * 16 + 8 + g) * 20 + ks * 8 + t4];
            a[ks][2] = as[(warp * 16 + g) * 20 + ks * 8 + t4 + 4];
            a[ks][3] = as[(warp * 16 + 8 + g) * 20 + ks * 8 + t4 + 4];
        }
        #pragma unroll
        for (int n8 = 0; n8 < 8; n8++) {
            #pragma unroll
            for (int ks = 0; ks < 2; ks++) {
                unsigned b0 = bs[(n8 * 8 + g) * 20 + ks * 8 + t4];
                unsigned b1 = bs[(n8 * 8 + g) * 20 + ks * 8 + t4 + 4];
                mma_bf16(acc[n8], a[ks], b0, b1);
            }
        }
    }

    int gm0 = m0 + warp * 16 + g;
    int gm1 = gm0 + 8;

    if (MODE == 1) {
        const float SCQ = 0.17677669529663687f * 1.4426950408889634f;  // 1/sqrt(32)*log2e
        int region = n0 >> 8;    // 0=Q, 1=K, 2=V
        int b0i = gm0 / Stok, s0 = gm0 - b0i * Stok;
        int b1i = gm1 / Stok, s1 = gm1 - b1i * Stok;
        #pragma unroll
        for (int n8 = 0; n8 < 8; n8++) {
            int col = n0 + n8 * 8 + 2 * t4;
            float2 bb2 = *(const float2*)(bias + col);
            float v0 = acc[n8][0] + bb2.x, v1 = acc[n8][1] + bb2.y;
            float v2 = acc[n8][2] + bb2.x, v3 = acc[n8][3] + bb2.y;
            if (region == 0) {
                if (gm0 < M && s0 < HW)
                    *(unsigned*)(g_qb + ((size_t)b0i * HW + s0) * 256 + col) =
                        pkbf(v0 * SCQ, v1 * SCQ);
                if (gm1 < M && s1 < HW)
                    *(unsigned*)(g_qb + ((size_t)b1i * HW + s1) * 256 + col) =
                        pkbf(v2 * SCQ, v3 * SCQ);
            } else if (region == 1) {
                // K: pair-permute within row: p -> 4*(p&3) + (p>>2)
                int p = (col & 31) >> 1, hh = (col >> 5) & 7;
                int ddp = 2 * ((p & 3) * 4 + (p >> 2));
                if (gm0 < M)
                    *(unsigned*)(g_Kb + ((size_t)(b0i * 8 + hh) * KPAD + s0) * 32 + ddp) = pkbf(v0, v1);
                if (gm1 < M)
                    *(unsigned*)(g_Kb + ((size_t)(b1i * 8 + hh) * KPAD + s1) * 32 + ddp) = pkbf(v2, v3);
            } else {
                // V: transposed store with per-tile key permutation
                int dd = col & 31, hh = (col >> 5) & 7;
                if (gm0 < M) {
                    int sp = vperm(s0);
                    bf16* base = g_VbT + (size_t)(b0i * 8 + hh) * 32 * KPAD;
                    base[(size_t)dd * KPAD + sp]       = __float2bfloat16_rn(v0);
                    base[(size_t)(dd + 1) * KPAD + sp] = __float2bfloat16_rn(v1);
                }
                if (gm1 < M) {
                    int sp = vperm(s1);
                    bf16* base = g_VbT + (size_t)(b1i * 8 + hh) * 32 * KPAD;
                    base[(size_t)dd * KPAD + sp]       = __float2bfloat16_rn(v2);
                    base[(size_t)(dd + 1) * KPAD + sp] = __float2bfloat16_rn(v3);
                }
            }
        }
        return;
    }

    if (MODE == 4) {
        float* C = (float*)Cv;
        int b0i = gm0 / HW, p0 = gm0 - b0i * HW;
        int b1i = gm1 / HW, p1 = gm1 - b1i * HW;
        #pragma unroll
        for (int n8 = 0; n8 < 8; n8++) {
            int col = n0 + n8 * 8 + 2 * t4;
            float2 bb2 = *(const float2*)(bias + col);
            float2 d0 = *(const float2*)(D + (size_t)gm0 * N + col);
            float2 d1 = *(const float2*)(D + (size_t)gm1 * N + col);
            size_t i00 = ((size_t)b0i * Cc + col) * HW + p0;
            size_t i01 = ((size_t)b0i * Cc + col + 1) * HW + p0;
            size_t i10 = ((size_t)b1i * Cc + col) * HW + p1;
            size_t i11 = ((size_t)b1i * Cc + col + 1) * HW + p1;
            C[i00] = acc[n8][0] + bb2.x + d0.x + X[i00];
            C[i01] = acc[n8][1] + bb2.y + d0.y + X[i01];
            C[i10] = acc[n8][2] + bb2.x + d1.x + X[i10];
            C[i11] = acc[n8][3] + bb2.y + d1.y + X[i11];
        }
        return;
    }

    #pragma unroll
    for (int n8 = 0; n8 < 8; n8++) {
        int col = n0 + n8 * 8 + 2 * t4;
        float2 bb2 = *(const float2*)(bias + col);
        float v0 = acc[n8][0] + bb2.x, v1 = acc[n8][1] + bb2.y;
        float v2 = acc[n8][2] + bb2.x, v3 = acc[n8][3] + bb2.y;
        if (ACT == 1) {
            v0 = gelu_exact(v0); v1 = gelu_exact(v1);
            v2 = gelu_exact(v2); v3 = gelu_exact(v3);
        }
        if (MODE == 2) {
            if (gm0 < M) {
                float2 d0 = *(const float2*)(D + (size_t)gm0 * N + col);
                v0 += d0.x; v1 += d0.y;
            }
            if (gm1 < M) {
                float2 d1 = *(const float2*)(D + (size_t)gm1 * N + col);
                v2 += d1.x; v3 += d1.y;
            }
        }
        if (MODE == 3) {
            bf16* C = (bf16*)Cv;
            if (gm0 < M) *(unsigned*)(C + (size_t)gm0 * N + col) = pkbf(v0, v1);
            if (gm1 < M) *(unsigned*)(C + (size_t)gm1 * N + col) = pkbf(v2, v3);
        } else {
            float* C = (float*)Cv;
            if (gm0 < M) *(float2*)(C + (size_t)gm0 * N + col) = make_float2(v0, v1);
            if (gm1 < M) *(float2*)(C + (size_t)gm1 * N + col) = make_float2(v2, v3);
        }
    }
}

// ---------------- layernorm: 2 rows per warp (interleaved reduce chains) ----------------
__global__ void k_ln(const float* __restrict__ in, int inTok,
                     const float* __restrict__ w, const float* __restrict__ bv,
                     bf16* __restrict__ out, int outTok)
{
    int wid = blockIdx.x * 8 + (threadIdx.x >> 5);
    int lane = threadIdx.x & 31;
    int rowA = wid * 2, rowB = rowA + 1;
    int bA = rowA / HW, pA = rowA % HW;
    int bB = rowB / HW, pB = rowB % HW;
    const float* srcA = in + ((size_t)bA * inTok + pA) * Cc;
    const float* srcB = in + ((size_t)bB * inTok + pB) * Cc;
    float4 a0 = *(const float4*)(srcA + lane * 4);
    float4 a1 = *(const float4*)(srcA + 128 + lane * 4);
    float4 b0 = *(const float4*)(srcB + lane * 4);
    float4 b1 = *(const float4*)(srcB + 128 + lane * 4);
    float sA = a0.x + a0.y + a0.z + a0.w + a1.x + a1.y + a1.z + a1.w;
    float sB = b0.x + b0.y + b0.z + b0.w + b1.x + b1.y + b1.z + b1.w;
    #pragma unroll
    for (int o = 16; o > 0; o >>= 1) {
        sA += __shfl_xor_sync(0xffffffffu, sA, o);
        sB += __shfl_xor_sync(0xffffffffu, sB, o);
    }
    float mA = sA * (1.0f / 256.0f), mB = sB * (1.0f / 256.0f);
    float dA[8] = {a0.x-mA, a0.y-mA, a0.z-mA, a0.w-mA, a1.x-mA, a1.y-mA, a1.z-mA, a1.w-mA};
    float dB[8] = {b0.x-mB, b0.y-mB, b0.z-mB, b0.w-mB, b1.x-mB, b1.y-mB, b1.z-mB, b1.w-mB};
    float vA = 0.f, vB = 0.f;
    #pragma unroll
    for (int i = 0; i < 8; i++) { vA += dA[i]*dA[i]; vB += dB[i]*dB[i]; }
    #pragma unroll
    for (int o = 16; o > 0; o >>= 1) {
        vA += __shfl_xor_sync(0xffffffffu, vA, o);
        vB += __shfl_xor_sync(0xffffffffu, vB, o);
    }
    float rA = rsqrtf(vA * (1.0f / 256.0f) + 1e-5f);
    float rB = rsqrtf(vB * (1.0f / 256.0f) + 1e-5f);
    float4 w0 = *(const float4*)(w + lane * 4);
    float4 w1 = *(const float4*)(w + 128 + lane * 4);
    float4 c0 = *(const float4*)(bv + lane * 4);
    float4 c1 = *(const float4*)(bv + 128 + lane * 4);
    float wr[8] = {w0.x, w0.y, w0.z, w0.w, w1.x, w1.y, w1.z, w1.w};
    float cr[8] = {c0.x, c0.y, c0.z, c0.w, c1.x, c1.y, c1.z, c1.w};
    bf16* dstA = out + ((size_t)bA * outTok + pA) * Cc;
    bf16* dstB = out + ((size_t)bB * outTok + pB) * Cc;
    uint2 oA0 = make_uint2(pkbf(dA[0]*rA*wr[0]+cr[0], dA[1]*rA*wr[1]+cr[1]),
                           pkbf(dA[2]*rA*wr[2]+cr[2], dA[3]*rA*wr[3]+cr[3]));
    uint2 oA1 = make_uint2(pkbf(dA[4]*rA*wr[4]+cr[4], dA[5]*rA*wr[5]+cr[5]),
                           pkbf(dA[6]*rA*wr[6]+cr[6], dA[7]*rA*wr[7]+cr[7]));
    uint2 oB0 = make_uint2(pkbf(dB[0]*rB*wr[0]+cr[0], dB[1]*rB*wr[1]+cr[1]),
                           pkbf(dB[2]*rB*wr[2]+cr[2], dB[3]*rB*wr[3]+cr[3]));
    uint2 oB1 = make_uint2(pkbf(dB[4]*rB*wr[4]+cr[4], dB[5]*rB*wr[5]+cr[5]),
                           pkbf(dB[6]*rB*wr[6]+cr[6], dB[7]*rB*wr[7]+cr[7]));
    *(uint2*)(dstA + lane * 4) = oA0;
    *(uint2*)(dstA + 128 + lane * 4) = oA1;
    *(uint2*)(dstB + lane * 4) = oB0;
    *(uint2*)(dstB + 128 + lane * 4) = oB1;
}

// ---------------- pooled LN, both scales in one launch ----------------
__global__ void k_pool_ln(const float* __restrict__ xp,
                          const float* __restrict__ w, const float* __restrict__ bv,
                          bf16* __restrict__ f)
{
    int b = blockIdx.y;
    int t = blockIdx.x;
    int ps, off, reg, tt;
    if (t < 144) { ps = 4; off = HW;       reg = 0; tt = t; }
    else         { ps = 8; off = HW + 144; reg = 1; tt = t - 144; }
    int gw = Ww / ps;
    int bh = tt / gw, bw = tt % gw;
    int c = threadIdx.x;
    float s = 0.f;
    for (int i = 0; i < ps; i++) {
        int prow = (bh * ps + i) * Ww + bw * ps;
        const float* base = xp + ((size_t)b * HW + prow) * Cc + c;
        for (int j = 0; j < ps; j++) s += base[(size_t)j * Cc];
    }
    float v = s / (float)(ps * ps);
    __shared__ float sb[8];
    float ss = v;
    #pragma unroll
    for (int o = 16; o > 0; o >>= 1) ss += __shfl_xor_sync(0xffffffffu, ss, o);
    if ((c & 31) == 0) sb[c >> 5] = ss;
    __syncthreads();
    float tot = 0.f;
    #pragma unroll
    for (int i = 0; i < 8; i++) tot += sb[i];
    float mean = tot * (1.0f / 256.0f);
    __syncthreads();
    float d = v - mean;
    float s2 = d * d;
    #pragma unroll
    for (int o = 16; o > 0; o >>= 1) s2 += __shfl_xor_sync(0xffffffffu, s2, o);
    if ((c & 31) == 0) sb[c >> 5] = s2;
    __syncthreads();
    float tot2 = 0.f;
    #pragma unroll
    for (int i = 0; i < 8; i++) tot2 += sb[i];
    float rs = rsqrtf(tot2 * (1.0f / 256.0f) + 1e-5f);
    f[((size_t)b * Stok + off + tt) * Cc + c] =
        __float2bfloat16_rn(d * rs * w[reg * Cc + c] + bv[reg * Cc + c]);
}

// ---------------- bf16 mma flash attention: vector-fragment loads ----------------
#define KV_TILES 39

__global__ void __launch_bounds__(256, 2) k_attn(const bf16* __restrict__ qv,
                                                 const bf16* __restrict__ Kb,
                                                 const bf16* __restrict__ VbT,
                                                 const unsigned* __restrict__ mb,
                                                 bf16* __restrict__ out)
{
    __shared__ __align__(16) unsigned char KsB[3][64 * 64];    // 64 rows x 64B (permuted pairs)
    __shared__ __align__(16) unsigned char VsB[3][32 * 160];   // 32 rows x 128B data + 32B pad
    __shared__ unsigned Msm[3][256];

    int tid  = threadIdx.x;
    int warp = tid >> 5, lane = tid & 31;
    int g = lane >> 2, t4 = lane & 3;
    int q0 = blockIdx.x * 128, h = blockIdx.y, b = blockIdx.z;
    int bh = b * 8 + h;

    const bf16* Kg = Kb  + (size_t)bh * KPAD * 32;
    const bf16* Vg = VbT + (size_t)bh * 32 * KPAD;
    const bf16* qb = qv + ((size_t)b * HW) * 256 + h * 32;

    int r0 = q0 + warp * 16 + g;
    int r1 = r0 + 8;

    // Q fragments: pre-scaled bf16 in gmem, plain 4B loads
    unsigned qa[2][4];
    #pragma unroll
    for (int ks = 0; ks < 2; ks++) {
        #pragma unroll
        for (int half = 0; half < 2; half++) {
            int kc = ks * 16 + half * 8 + 2 * t4;
            qa[ks][half * 2 + 0] = *(const unsigned*)(qb + (size_t)r0 * 256 + kc);
            qa[ks][half * 2 + 1] = *(const unsigned*)(qb + (size_t)r1 * 256 + kc);
        }
    }

    auto issue = [&](int kt) {
        int k0 = kt * 64;
        int st = kt % 3;
        {
            int row = tid >> 2, c = tid & 3;
            cpa16(&KsB[st][row * 64 + c * 16], Kg + (size_t)(k0 + row) * 32 + c * 8);
        }
        {
            int d = tid >> 3, c = tid & 7;
            cpa16(&VsB[st][d * 160 + c * 16], Vg + (size_t)d * KPAD + k0 + c * 8);
        }
        cpa_commit();
        if (tid < 128) {
            int row = tid, gq = q0 + row;
            Msm[st][row * 2]     = mb[(size_t)gq * NW + kt * 2];
            Msm[st][row * 2 + 1] = mb[(size_t)gq * NW + kt * 2 + 1];
        }
    };

    float l0 = 0.f, l1 = 0.f;
    float o[4][4] = {};

    issue(0);
    issue(1);
    for (int kt = 0; kt < KV_TILES; kt++) {
        if (kt + 1 < KV_TILES) cpa_wait1(); else cpa_wait0();
        __syncthreads();
        if (kt + 2 < KV_TILES) issue(kt + 2);

        int cur = kt % 3;
        const unsigned char* KwB = KsB[cur];
        const unsigned char* VwB = VsB[cur];

        unsigned w00 = Msm[cur][(warp * 16 + g) * 2 + 0];
        unsigned w01 = Msm[cur][(warp * 16 + g) * 2 + 1];
        unsigned w10 = Msm[cur][(warp * 16 + 8 + g) * 2 + 0];
        unsigned w11 = Msm[cur][(warp * 16 + 8 + g) * 2 + 1];

        float rs0 = 0.f, rs1 = 0.f;

        #pragma unroll
        for (int j = 0; j < 4; j++) {
            int n8a = 2 * j, n8b = 2 * j + 1;
            // K fragments: one LDS.128 per key-group (pair-permuted rows)
            uint4 ka  = *(const uint4*)(KwB + (n8a * 8 + g) * 64 + t4 * 16);
            uint4 kb2 = *(const uint4*)(KwB + (n8b * 8 + g) * 64 + t4 * 16);
            float s0[4] = {0.f, 0.f, 0.f, 0.f};
            float s1[4] = {0.f, 0.f, 0.f, 0.f};
            mma_bf16(s0, qa[0], ka.x, ka.y);
            mma_bf16(s0, qa[1], ka.z, ka.w);
            mma_bf16(s1, qa[0], kb2.x, kb2.y);
            mma_bf16(s1, qa[1], kb2.z, kb2.w);

            unsigned mr0 = (j < 2) ? w00 : w01;
            unsigned mr1 = (j < 2) ? w10 : w11;
            int sha = (n8a * 8 + 2 * t4) & 31;
            int shb = (n8b * 8 + 2 * t4) & 31;
            if ((mr0 >> sha) & 1u)        s0[0] = -1.0e9f;
            if ((mr0 >> (sha + 1)) & 1u)  s0[1] = -1.0e9f;
            if ((mr1 >> sha) & 1u)        s0[2] = -1.0e9f;
            if ((mr1 >> (sha + 1)) & 1u)  s0[3] = -1.0e9f;
            if ((mr0 >> shb) & 1u)        s1[0] = -1.0e9f;
            if ((mr0 >> (shb + 1)) & 1u)  s1[1] = -1.0e9f;
            if ((mr1 >> shb) & 1u)        s1[2] = -1.0e9f;
            if ((mr1 >> (shb + 1)) & 1u)  s1[3] = -1.0e9f;
            s0[0] = ex2(s0[0]); s0[1] = ex2(s0[1]);
            s0[2] = ex2(s0[2]); s0[3] = ex2(s0[3]);
            s1[0] = ex2(s1[0]); s1[1] = ex2(s1[1]);
            s1[2] = ex2(s1[2]); s1[3] = ex2(s1[3]);
            rs0 += s0[0] + s0[1] + s1[0] + s1[1];
            rs1 += s0[2] + s0[3] + s1[2] + s1[3];
            unsigned paj[4];
            paj[0] = pkbf(s0[0], s0[1]);
            paj[1] = pkbf(s0[2], s0[3]);
            paj[2] = pkbf(s1[0], s1[1]);
            paj[3] = pkbf(s1[2], s1[3]);
            // V fragments: one LDS.64 per d8 (per-tile key-permuted)
            #pragma unroll
            for (int d8 = 0; d8 < 4; d8++) {
                uint2 vv = *(const uint2*)(VwB + (d8 * 8 + g) * 160 + (j * 8 + 2 * t4) * 4);
                mma_bf16(o[d8], paj, vv.x, vv.y);
            }
        }
        l0 += rs0;
        l1 += rs1;
    }

    l0 += __shfl_xor_sync(0xffffffffu, l0, 1);
    l0 += __shfl_xor_sync(0xffffffffu, l0, 2);
    l1 += __shfl_xor_sync(0xffffffffu, l1, 1);
    l1 += __shfl_xor_sync(0xffffffffu, l1, 2);
    float inv0 = 1.0f / l0, inv1 = 1.0f / l1;
    #pragma unroll
    for (int d8 = 0; d8 < 4; d8++) {
        int dc = h * 32 + d8 * 8 + 2 * t4;
        *(unsigned*)(out + ((size_t)b * HW + r0) * 256 + dc) =
            pkbf(o[d8][0] * inv0, o[d8][1] * inv0);
        *(unsigned*)(out + ((size_t)b * HW + r1) * 256 + dc) =
            pkbf(o[d8][2] * inv1, o[d8][3] * inv1);
    }
}

// ---------------- launch ----------------
extern "C" void kernel_launch(void* const* d_in, const int* in_sizes, int n_in,
                              void* d_out, int out_size)
{
    const float* x          = (const float*)d_in[0];
    const float* conv_w     = (const float*)d_in[1];
    const float* conv_b     = (const float*)d_in[2];
    const float* ln_local_w = (const float*)d_in[3];
    const float* ln_local_b = (const float*)d_in[4];
    const float* ln_reg_w   = (const float*)d_in[5];
    const float* ln_reg_b   = (const float*)d_in[6];
    const float* in_proj_w  = (const float*)d_in[7];
    const float* in_proj_b  = (const float*)d_in[8];
    const float* out_proj_w = (const float*)d_in[9];
    const float* out_proj_b = (const float*)d_in[10];
    const float* ln_out_w   = (const float*)d_in[11];
    const float* ln_out_b   = (const float*)d_in[12];
    const float* mlp_w1     = (const float*)d_in[13];
    const float* mlp_b1     = (const float*)d_in[14];
    const float* mlp_w2     = (const float*)d_in[15];
    const float* mlp_b2     = (const float*)d_in[16];
    const void*  attn_mask  = (const void*)d_in[17];
    float* out = (float*)d_out;

    float *xp, *op;
    bf16 *f, *qbp, *ob, *hid, *m1, *Kb, *VbT, *wqkv, *wout, *wm1, *wm2;
    unsigned* mbp;
    cudaGetSymbolAddress((void**)&xp,  g_xp);
    cudaGetSymbolAddress((void**)&f,   g_f);
    cudaGetSymbolAddress((void**)&qbp, g_qb);
    cudaGetSymbolAddress((void**)&ob,  g_ob);
    cudaGetSymbolAddress((void**)&op,  g_op);
    cudaGetSymbolAddress((void**)&hid, g_hid);
    cudaGetSymbolAddress((void**)&m1,  g_m1);
    cudaGetSymbolAddress((void**)&mbp, g_mb);
    cudaGetSymbolAddress((void**)&Kb,  g_Kb);
    cudaGetSymbolAddress((void**)&VbT, g_VbT);
    cudaGetSymbolAddress((void**)&wqkv, g_wqkv);
    cudaGetSymbolAddress((void**)&wout, g_wout);
    cudaGetSymbolAddress((void**)&wm1,  g_wm1);
    cudaGetSymbolAddress((void**)&wm2,  g_wm2);

    // merged preamble (1 launch)
    k_pre<<<MASK_BLOCKS + CVT_BLOCKS, 256>>>(attn_mask, mbp,
                                             in_proj_w, out_proj_w, mlp_w1, mlp_w2);

    // conv (1x1), reading x[b][c][p] directly (fused transpose, tf32)
    k_conv<<<dim3(Cc / 64, (Bz * HW) / 128), 256>>>(x, conv_w, conv_b, xp, Bz * HW, Cc, Cc);

    // feats: LN local + pooled LN (bf16 out), pooled scales merged
    k_ln<<<Bz * HW / 16, 256>>>(xp, HW, ln_local_w, ln_local_b, f, Stok);
    k_pool_ln<<<dim3(180, Bz), 256>>>(xp, ln_reg_w, ln_reg_b, f);

    // qkv bf16 GEMM, split epilogue: Q -> g_qb (pre-scaled bf16), K/V permuted layouts
    k_bgemm<0, 1><<<dim3(768 / 64, (Bz * Stok + 127) / 128), 256>>>(
        f, wqkv, in_proj_b, nullptr, nullptr, nullptr, Bz * Stok, 3 * Cc, Cc);

    // attention — BQ=128, 2 CTAs/SM; vector-fragment loads; bf16 output
    k_attn<<<dim3(HW / 128, 8, Bz), 256>>>(qbp, Kb, VbT, mbp, ob);

    // out_proj (bf16 in, f32 out)
    k_bgemm<0, 0><<<dim3(Cc / 64, (Bz * HW) / 128), 256>>>(
        ob, wout, out_proj_b, nullptr, nullptr, op, Bz * HW, Cc, Cc);

    // ln_out on local tokens (bf16 out)
    k_ln<<<Bz * HW / 16, 256>>>(op, HW, ln_out_w, ln_out_b, hid, HW);

    // mlp: mlp1 bf16->bf16 with GELU; mlp2 fused transposed final store (+op residual +x)
    k_bgemm<1, 3><<<dim3(BOT / 64, (Bz * HW) / 128), 256>>>(
        hid, wm1, mlp_b1, nullptr, nullptr, m1, Bz * HW, BOT, Cc);
    k_bgemm<0, 4><<<dim3(Cc / 64, (Bz * HW) / 128), 256>>>(
        m1, wm2, mlp_b2, op, x, out, Bz * HW, Cc, BOT);
}